// round 8
// baseline (speedup 1.0000x reference)
#include <cuda_runtime.h>
#include <math.h>

// ---------------- problem constants ----------------
#define Bc   8
#define Nn   64
#define Dd   128
#define Hh   4
#define DHc  32
#define FFc  512
#define Lc   3
#define TOK  (Bc*Nn*Nn)              // 32768 tokens
#define QKVW 512                     // fused q|k|v1|v2 width
#define SCALE_INV 0.17677669529663687f   // 1/sqrt(32)

typedef unsigned long long ull;

// ---------------- device scratch (allowed: __device__ globals) ----------------
__device__ float g_tok [TOK*Dd];           // 16 MB
__device__ float g_qkv [TOK*QKVW];         // 67 MB  [tok][q|k|v1|v2]
__device__ float g_s   [Bc*Hh*Nn*Nn*Nn];   // 33.5 MB, [b][h][l][i][j]
__device__ float g_o   [TOK*Dd];           // 16 MB
__device__ float g_hid [TOK*FFc];          // 64 MB
__device__ float g_wqkv[Lc*Dd*QKVW];       // 0.8 MB packed per-layer QKV weights

// ---------------- packed f32x2 fma ----------------
__device__ __forceinline__ ull ffma2(ull a, ull b, ull c) {
    ull d;
    asm("fma.rn.f32x2 %0, %1, %2, %3;" : "=l"(d) : "l"(a), "l"(b), "l"(c));
    return d;
}
__device__ __forceinline__ float lo32(ull v) { return __uint_as_float((unsigned)(v & 0xffffffffull)); }
__device__ __forceinline__ float hi32(ull v) { return __uint_as_float((unsigned)(v >> 32)); }

// ---------------- pack Wq|Wk|Wv1|Wv2 -> g_wqkv [l][c][512] ----------------
__global__ void pack_qkv_kernel(const float* __restrict__ Wq, const float* __restrict__ Wk,
                                const float* __restrict__ Wv1, const float* __restrict__ Wv2)
{
    int idx = blockIdx.x * 256 + threadIdx.x;       // over Lc*128*512
    int l = idx >> 16;
    int c = (idx >> 9) & 127;
    int n = idx & 511;
    int col = n & 127;
    const float* src;
    switch (n >> 7) {
        case 0:  src = Wq;  break;
        case 1:  src = Wk;  break;
        case 2:  src = Wv1; break;
        default: src = Wv2; break;
    }
    g_wqkv[idx] = src[((size_t)l*Dd + c)*Dd + col];
}

// ---------------- embedding ----------------
__global__ void embed_kernel(const float* __restrict__ x,
                             const float* __restrict__ ea,
                             const unsigned int* __restrict__ mask,
                             const float* __restrict__ nW, const float* __restrict__ nb,
                             const float* __restrict__ eW, const float* __restrict__ eb,
                             const float* __restrict__ noe)
{
    int tkn = blockIdx.x;
    int b   = tkn >> 12;
    int ij  = tkn & 4095;
    int i   = ij >> 6, j = ij & 63;
    int d   = threadIdx.x;
    __shared__ float s_in[16];
    float out;
    if (i == j) {
        if (d < 16) s_in[d] = x[(b*Nn + i)*16 + d];
        __syncthreads();
        float acc = nb[d];
#pragma unroll
        for (int c = 0; c < 16; c++) acc += s_in[c] * nW[c*Dd + d];
        out = acc;
    } else {
        if (d < 8) s_in[d] = ea[tkn*8 + d];
        __syncthreads();
        if (mask[tkn] != 0u) {
            float acc = eb[d];
#pragma unroll
            for (int c = 0; c < 8; c++) acc += s_in[c] * eW[c*Dd + d];
            out = acc;
        } else {
            out = noe[d];
        }
    }
    g_tok[tkn*Dd + d] = out;
}

// ---------------- 128x128 SGEMM, BK=8, 8x8/thread, packed f32x2 FMA ----------
// C[M x N] = A[M x K] @ W[K x N]  (+bias) (+residual) (ReLU) (LN over N=128)
template<bool RELU, bool RESID, bool LN>
__global__ void __launch_bounds__(256, 2)
gemm128(const float* __restrict__ A, const float* __restrict__ W,
        const float* __restrict__ bias, const float* __restrict__ resid,
        const float* __restrict__ lng,  const float* __restrict__ lnb,
        float* __restrict__ C, int K, int N)
{
    __shared__ float As2[8][256];   // A values duplicated: [k][2m]=[k][2m+1]=A[m][k]
    __shared__ float Bs [8][128];
    const int t   = threadIdx.x;
    const int bm0 = blockIdx.y * 128;
    const int bn0 = blockIdx.x * 128;
    const int tx  = t & 15, ty = t >> 4;

    ull acc[8][4];
#pragma unroll
    for (int i = 0; i < 8; i++)
#pragma unroll
        for (int j = 0; j < 4; j++) acc[i][j] = 0ull;

    const int am  = t >> 1;
    const int akq = (t & 1) * 4;
    const int bkr = t >> 5;
    const int bnc = (t & 31) * 4;
    const float* Aptr = A + (size_t)(bm0 + am) * K + akq;
    const float* Wptr = W + (size_t)bkr * N + bn0 + bnc;

    for (int k0 = 0; k0 < K; k0 += 8) {
        float4 av = *(const float4*)(Aptr + k0);
        float4 wv = *(const float4*)(Wptr + (size_t)k0 * N);
        // duplicated A stores (float2 {v,v})
        *(float2*)&As2[akq+0][2*am] = make_float2(av.x, av.x);
        *(float2*)&As2[akq+1][2*am] = make_float2(av.y, av.y);
        *(float2*)&As2[akq+2][2*am] = make_float2(av.z, av.z);
        *(float2*)&As2[akq+3][2*am] = make_float2(av.w, av.w);
        *(float4*)&Bs[bkr][bnc] = wv;
        __syncthreads();
#pragma unroll
        for (int kk = 0; kk < 8; kk++) {
            ulonglong2 aA = *(const ulonglong2*)&As2[kk][ty*16 + 0];
            ulonglong2 aB = *(const ulonglong2*)&As2[kk][ty*16 + 4];
            ulonglong2 aC = *(const ulonglong2*)&As2[kk][ty*16 + 8];
            ulonglong2 aD = *(const ulonglong2*)&As2[kk][ty*16 + 12];
            ulonglong2 b0 = *(const ulonglong2*)&Bs[kk][tx*8 + 0];
            ulonglong2 b1 = *(const ulonglong2*)&Bs[kk][tx*8 + 4];
            ull a[8] = {aA.x, aA.y, aB.x, aB.y, aC.x, aC.y, aD.x, aD.y};
            ull b[4] = {b0.x, b0.y, b1.x, b1.y};
#pragma unroll
            for (int i = 0; i < 8; i++)
#pragma unroll
                for (int j = 0; j < 4; j++)
                    acc[i][j] = ffma2(a[i], b[j], acc[i][j]);
        }
        __syncthreads();
    }

    const int col0 = bn0 + tx*8;
    float bv[8];
#pragma unroll
    for (int j = 0; j < 8; j++) bv[j] = (bias != nullptr) ? bias[col0 + j] : 0.f;

#pragma unroll
    for (int i = 0; i < 8; i++) {
        int row = bm0 + ty*8 + i;
        float v[8];
#pragma unroll
        for (int j2 = 0; j2 < 4; j2++) {
            v[2*j2]   = lo32(acc[i][j2]);
            v[2*j2+1] = hi32(acc[i][j2]);
        }
        if (RESID) {
            float4 r0 = *(const float4*)&resid[(size_t)row*N + col0];
            float4 r1 = *(const float4*)&resid[(size_t)row*N + col0 + 4];
            float rr[8] = {r0.x,r0.y,r0.z,r0.w,r1.x,r1.y,r1.z,r1.w};
#pragma unroll
            for (int j = 0; j < 8; j++) v[j] += bv[j] + rr[j];
        } else {
#pragma unroll
            for (int j = 0; j < 8; j++) v[j] += bv[j];
        }
        if (RELU) {
#pragma unroll
            for (int j = 0; j < 8; j++) v[j] = fmaxf(v[j], 0.f);
        }
        if (LN) {
            float s1 = 0.f, s2 = 0.f;
#pragma unroll
            for (int j = 0; j < 8; j++) { s1 += v[j]; s2 += v[j]*v[j]; }
#pragma unroll
            for (int m = 8; m > 0; m >>= 1) {
                s1 += __shfl_xor_sync(0xffffffffu, s1, m);
                s2 += __shfl_xor_sync(0xffffffffu, s2, m);
            }
            float mean = s1 * (1.f/128.f);
            float var  = s2 * (1.f/128.f) - mean*mean;
            float rstd = rsqrtf(var + 1e-5f);
#pragma unroll
            for (int j = 0; j < 8; j++)
                v[j] = (v[j] - mean) * rstd * lng[col0 + j] + lnb[col0 + j];
        }
        *(float4*)&C[(size_t)row*N + col0]     = make_float4(v[0],v[1],v[2],v[3]);
        *(float4*)&C[(size_t)row*N + col0 + 4] = make_float4(v[4],v[5],v[6],v[7]);
    }
}

// ---------------- attention scores: per (b,h,l): s[i][j] = q_i . k_j / SCALE ----
__global__ void __launch_bounds__(256) attn_s_kernel()
{
    const int l = blockIdx.x, h = blockIdx.y, b = blockIdx.z;
    __shared__ float Qs[32][64];   // [d][i]
    __shared__ float Ks[32][64];   // [d][j]
    const int t = threadIdx.x;
    {
        int r  = t >> 2;
        int dq = (t & 3) * 8;
        const float* qp = g_qkv + ((size_t)((b*Nn + r)*Nn + l))*QKVW + h*DHc + dq;
        const float* kp = g_qkv + ((size_t)((b*Nn + l)*Nn + r))*QKVW + 128 + h*DHc + dq;
        float4 q0 = *(const float4*)qp, q1 = *(const float4*)(qp+4);
        float4 k0 = *(const float4*)kp, k1 = *(const float4*)(kp+4);
        Qs[dq+0][r]=q0.x; Qs[dq+1][r]=q0.y; Qs[dq+2][r]=q0.z; Qs[dq+3][r]=q0.w;
        Qs[dq+4][r]=q1.x; Qs[dq+5][r]=q1.y; Qs[dq+6][r]=q1.z; Qs[dq+7][r]=q1.w;
        Ks[dq+0][r]=k0.x; Ks[dq+1][r]=k0.y; Ks[dq+2][r]=k0.z; Ks[dq+3][r]=k0.w;
        Ks[dq+4][r]=k1.x; Ks[dq+5][r]=k1.y; Ks[dq+6][r]=k1.z; Ks[dq+7][r]=k1.w;
    }
    __syncthreads();
    const int tx = t & 15, ty = t >> 4;
    float acc[4][4];
#pragma unroll
    for (int i = 0; i < 4; i++)
#pragma unroll
        for (int j = 0; j < 4; j++) acc[i][j] = 0.f;
#pragma unroll
    for (int d = 0; d < 32; d++) {
        float4 a = *(const float4*)&Qs[d][ty*4];
        float4 c = *(const float4*)&Ks[d][tx*4];
        float av[4] = {a.x,a.y,a.z,a.w};
        float cv[4] = {c.x,c.y,c.z,c.w};
#pragma unroll
        for (int i = 0; i < 4; i++)
#pragma unroll
            for (int j = 0; j < 4; j++)
                acc[i][j] += av[i]*cv[j];
    }
    float* sp = g_s + ((size_t)((b*Hh + h)*Nn + l)) * 4096;
#pragma unroll
    for (int i = 0; i < 4; i++) {
        *(float4*)&sp[(ty*4 + i)*64 + tx*4] =
            make_float4(acc[i][0]*SCALE_INV, acc[i][1]*SCALE_INV,
                        acc[i][2]*SCALE_INV, acc[i][3]*SCALE_INV);
    }
}

// ---------------- softmax over l + o = sum_l a * (v1 ⊙ v2), per (b,h,i) --------
__global__ void __launch_bounds__(256) attn_ao_kernel()
{
    const int i = blockIdx.x, h = blockIdx.y, b = blockIdx.z;
    __shared__ float Aa[64][64];       // [l][j]
    __shared__ float V1s[64][32];      // [l][d]
    __shared__ float redA[4][64];
    __shared__ float redB[4][64];
    const int t = threadIdx.x;

    {
        const int j = t & 63, g = t >> 6;
        const float* sp = g_s + ((size_t)(b*Hh + h)*Nn) * 4096 + i*64 + j;
        float sv[16];
#pragma unroll
        for (int u = 0; u < 16; u++) sv[u] = sp[(size_t)(g*16 + u) * 4096];
        float m = sv[0];
#pragma unroll
        for (int u = 1; u < 16; u++) m = fmaxf(m, sv[u]);
        redA[g][j] = m;
        __syncthreads();
        float cm = fmaxf(fmaxf(redA[0][j], redA[1][j]), fmaxf(redA[2][j], redA[3][j]));
        float lsum = 0.f;
#pragma unroll
        for (int u = 0; u < 16; u++) { sv[u] = __expf(sv[u] - cm); lsum += sv[u]; }
        redB[g][j] = lsum;
        __syncthreads();
        float inv = 1.f / (redB[0][j] + redB[1][j] + redB[2][j] + redB[3][j]);
#pragma unroll
        for (int u = 0; u < 16; u++) Aa[g*16 + u][j] = sv[u] * inv;
    }
    {
        int l  = t >> 2;
        int dq = (t & 3) * 8;
        const float* vp = g_qkv + ((size_t)((b*Nn + i)*Nn + l))*QKVW + 256 + h*DHc + dq;
        *(float4*)&V1s[l][dq]   = *(const float4*)vp;
        *(float4*)&V1s[l][dq+4] = *(const float4*)(vp + 4);
    }
    __syncthreads();

    const int jj = t >> 2;
    const int dq = (t & 3) * 8;
    float acc[8];
#pragma unroll
    for (int u = 0; u < 8; u++) acc[u] = 0.f;
    const float* v2base = g_qkv + ((size_t)(b*Nn)*Nn + jj)*QKVW + 384 + h*DHc + dq;
#pragma unroll 4
    for (int l = 0; l < 64; l++) {
        float av = Aa[l][jj];
        float4 w0 = *(const float4*)&V1s[l][dq];
        float4 w1 = *(const float4*)&V1s[l][dq+4];
        float4 u0 = *(const float4*)(v2base + (size_t)l*Nn*QKVW);
        float4 u1 = *(const float4*)(v2base + (size_t)l*Nn*QKVW + 4);
        acc[0] += av * (w0.x * u0.x);
        acc[1] += av * (w0.y * u0.y);
        acc[2] += av * (w0.z * u0.z);
        acc[3] += av * (w0.w * u0.w);
        acc[4] += av * (w1.x * u1.x);
        acc[5] += av * (w1.y * u1.y);
        acc[6] += av * (w1.z * u1.z);
        acc[7] += av * (w1.w * u1.w);
    }
    float* op = g_o + ((size_t)((b*Nn + i)*Nn + jj))*Dd + h*DHc + dq;
    *(float4*)op       = make_float4(acc[0],acc[1],acc[2],acc[3]);
    *(float4*)(op + 4) = make_float4(acc[4],acc[5],acc[6],acc[7]);
}

// ---------------- final readout: diag tokens @ Wout + bout ----------------
__global__ void out_kernel(const float* __restrict__ Wout,
                           const float* __restrict__ bout,
                           float* __restrict__ out)
{
    int w    = (blockIdx.x * blockDim.x + threadIdx.x) >> 5;
    int lane = threadIdx.x & 31;
    if (w >= Bc*Nn) return;
    int b = w >> 6, n = w & 63;
    const float* tp = g_tok + ((size_t)((b*Nn + n)*Nn + n)) * Dd;
    float4 tv = *(const float4*)(tp + lane*4);
    float4 wv = *(const float4*)(Wout + lane*4);
    float s = tv.x*wv.x + tv.y*wv.y + tv.z*wv.z + tv.w*wv.w;
#pragma unroll
    for (int m = 16; m > 0; m >>= 1) s += __shfl_xor_sync(0xffffffffu, s, m);
    if (lane == 0) out[w] = s + bout[0];
}

// ---------------- host launcher ----------------
extern "C" void kernel_launch(void* const* d_in, const int* in_sizes, int n_in,
                              void* d_out, int out_size)
{
    const float*        x        = (const float*)d_in[0];
    const float*        ea       = (const float*)d_in[1];
    const unsigned int* mask     = (const unsigned int*)d_in[2];
    const float*        node_W   = (const float*)d_in[3];
    const float*        node_b   = (const float*)d_in[4];
    const float*        edge_W   = (const float*)d_in[5];
    const float*        edge_b   = (const float*)d_in[6];
    const float*        no_edge  = (const float*)d_in[7];
    const float*        Wq       = (const float*)d_in[8];
    const float*        Wk       = (const float*)d_in[9];
    const float*        Wv1      = (const float*)d_in[10];
    const float*        Wv2      = (const float*)d_in[11];
    const float*        Wo       = (const float*)d_in[12];
    const float*        bo       = (const float*)d_in[13];
    const float*        ln1g     = (const float*)d_in[14];
    const float*        ln1b     = (const float*)d_in[15];
    const float*        W1       = (const float*)d_in[16];
    const float*        b1       = (const float*)d_in[17];
    const float*        W2       = (const float*)d_in[18];
    const float*        b2       = (const float*)d_in[19];
    const float*        ln2g     = (const float*)d_in[20];
    const float*        ln2b     = (const float*)d_in[21];
    const float*        Wout     = (const float*)d_in[22];
    const float*        bout     = (const float*)d_in[23];

    float *tok, *qkv, *o, *hid, *wqkv;
    cudaGetSymbolAddress((void**)&tok,  g_tok);
    cudaGetSymbolAddress((void**)&qkv,  g_qkv);
    cudaGetSymbolAddress((void**)&o,    g_o);
    cudaGetSymbolAddress((void**)&hid,  g_hid);
    cudaGetSymbolAddress((void**)&wqkv, g_wqkv);

    pack_qkv_kernel<<<(Lc*Dd*QKVW)/256, 256>>>(Wq, Wk, Wv1, Wv2);
    embed_kernel<<<TOK, 128>>>(x, ea, mask, node_W, node_b, edge_W, edge_b, no_edge);

    const dim3 g1(1, TOK/128);    // N=128
    const dim3 g4(4, TOK/128);    // N=512
    const dim3 ga(Nn, Hh, Bc);

    for (int l = 0; l < Lc; l++) {
        size_t wOff  = (size_t)l * Dd * Dd;
        size_t bOff  = (size_t)l * Dd;
        size_t w1Off = (size_t)l * Dd * FFc;
        size_t b1Off = (size_t)l * FFc;

        // fused QKV: [TOK,128] @ [128,512]
        gemm128<false,false,false><<<g4,256>>>(tok, wqkv + (size_t)l*Dd*QKVW,
                                               nullptr, nullptr, nullptr, nullptr,
                                               qkv, Dd, QKVW);

        attn_s_kernel <<<ga,256>>>();
        attn_ao_kernel<<<ga,256>>>();

        // tok = LN(tok + o @ Wo + bo)
        gemm128<false,true,true><<<g1,256>>>(o, Wo + wOff, bo + bOff, tok,
                                             ln1g + bOff, ln1b + bOff, tok, Dd, Dd);
        // hid = relu(tok @ W1 + b1)
        gemm128<true,false,false><<<g4,256>>>(tok, W1 + w1Off, b1 + b1Off,
                                              nullptr, nullptr, nullptr, hid, Dd, FFc);
        // tok = LN(tok + hid @ W2 + b2)
        gemm128<false,true,true><<<g1,256>>>(hid, W2 + w1Off, b2 + bOff, tok,
                                             ln2g + bOff, ln2b + bOff, tok, FFc, Dd);
    }

    out_kernel<<<(Bc*Nn*32 + 255)/256, 256>>>(Wout, bout, (float*)d_out);
}

// round 11
// speedup vs baseline: 1.3230x; 1.3230x over previous
#include <cuda_runtime.h>
#include <cuda_bf16.h>
#include <math.h>
#include <stdint.h>

// ---------------- problem constants ----------------
#define Bc   8
#define Nn   64
#define Dd   128
#define Hh   4
#define DHc  32
#define FFc  512
#define Lc   3
#define TOK  (Bc*Nn*Nn)              // 32768 tokens
#define QKVW 512
#define SCALE_INV 0.17677669529663687f

typedef unsigned long long ull;

// tcgen05 is only legal in arch-specific compilation (sm_103a / sm_100a).
// The harness also emits a compute_103 PTX pass, which must get the fallback.
#if defined(__CUDA_ARCH__) && (defined(__CUDA_ARCH_FEAT_SM103_ALL) || \
    defined(__CUDA_ARCH_FEAT_SM100_ALL) || defined(__CUDA_ARCH_SPECIFIC__) || \
    defined(__CUDA_ARCH_FAMILY_SPECIFIC__))
#define TC_OK 1
#else
#define TC_OK 0
#endif

// ---------------- device scratch ----------------
__device__ float g_tok [TOK*Dd];
__device__ float g_qkv [TOK*QKVW];
__device__ float g_s   [Bc*Hh*Nn*Nn*Nn];
__device__ float g_o   [TOK*Dd];
__device__ float g_hid [TOK*FFc];
__device__ float g_wqkv[Lc*Dd*QKVW];
// packed bf16 hi/lo weights, swizzled blocked-atom tiles of 128x128 (16384 el)
__device__ __nv_bfloat16 g_wh_qkv[Lc*4*16384], g_wl_qkv[Lc*4*16384];
__device__ __nv_bfloat16 g_wh_wo [Lc*1*16384], g_wl_wo [Lc*1*16384];
__device__ __nv_bfloat16 g_wh_w1 [Lc*4*16384], g_wl_w1 [Lc*4*16384];
__device__ __nv_bfloat16 g_wh_w2 [Lc*4*16384], g_wl_w2 [Lc*4*16384];

// ---------------- tcgen05 helpers ----------------
__device__ __forceinline__ uint32_t smem_u32(const void* p) {
    uint32_t a;
    asm("{ .reg .u64 t; cvta.to.shared.u64 t, %1; cvt.u32.u64 %0, t; }" : "=r"(a) : "l"(p));
    return a;
}
__device__ __forceinline__ uint32_t elect_one() {
    uint32_t pred;
    asm volatile("{\n\t.reg .pred p;\n\telect.sync _|p, 0xFFFFFFFF;\n\tselp.b32 %0, 1, 0, p;\n\t}" : "=r"(pred));
    return pred;
}
#define TC_ALLOC(sa, n)   asm volatile("tcgen05.alloc.cta_group::1.sync.aligned.shared::cta.b32 [%0], %1;" :: "r"((uint32_t)(sa)), "r"((uint32_t)(n)) : "memory")
#define TC_DEALLOC(ta, n) asm volatile("tcgen05.dealloc.cta_group::1.sync.aligned.b32 %0, %1;" :: "r"(ta), "r"((uint32_t)(n)))
#define TC_COMMIT(mb)     asm volatile("tcgen05.commit.cta_group::1.mbarrier::arrive::one.shared::cluster.b64 [%0];" :: "r"((uint32_t)(mb)) : "memory")
#define TC_FENCE_AFTER()  asm volatile("tcgen05.fence::after_thread_sync;" ::: "memory")
#define TC_FENCE_BEFORE() asm volatile("tcgen05.fence::before_thread_sync;" ::: "memory")
#define TC_WAIT_LD()      asm volatile("tcgen05.wait::ld.sync.aligned;" ::: "memory")
#define FENCE_ASYNC()     asm volatile("fence.proxy.async.shared::cta;" ::: "memory")
#define MBAR_INIT(mb, c)  asm volatile("mbarrier.init.shared.b64 [%0], %1;" :: "r"((uint32_t)(mb)), "r"((uint32_t)(c)) : "memory")
#define MBAR_INVAL(mb)    asm volatile("mbarrier.inval.shared.b64 [%0];" :: "r"((uint32_t)(mb)) : "memory")

#define MBAR_WAIT(mb, par) do {                                              \
    uint32_t _mb = (uint32_t)(mb), _p = (uint32_t)(par), _done;              \
    asm volatile("{\n\t.reg .pred p;\n\t"                                    \
        "mbarrier.try_wait.parity.acquire.cta.shared::cta.b64 p, [%1], %2;\n\t" \
        "selp.b32 %0, 1, 0, p;\n\t}" : "=r"(_done) : "r"(_mb), "r"(_p) : "memory"); \
    if (!_done) {                                                            \
        asm volatile("{\n\t.reg .pred P1;\n\t"                               \
            "WAIT_LOOP_%=:\n\t"                                              \
            "mbarrier.try_wait.parity.acquire.cta.shared::cta.b64 P1, [%0], %1, 0x989680;\n\t" \
            "@P1 bra.uni WAIT_DONE_%=;\n\tbra.uni WAIT_LOOP_%=;\n\t"          \
            "WAIT_DONE_%=:\n\t}" :: "r"(_mb), "r"(_p) : "memory");           \
    }                                                                        \
} while (0)

#define TC_LD_X32(r, ta)                                                     \
    asm volatile("tcgen05.ld.sync.aligned.32x32b.x32.b32 "                   \
        "{%0, %1, %2, %3, %4, %5, %6, %7, "                                  \
        " %8, %9, %10, %11, %12, %13, %14, %15, "                            \
        " %16, %17, %18, %19, %20, %21, %22, %23, "                          \
        " %24, %25, %26, %27, %28, %29, %30, %31}, [%32];"                   \
        : "=r"((r)[0]),  "=r"((r)[1]),  "=r"((r)[2]),  "=r"((r)[3]),         \
          "=r"((r)[4]),  "=r"((r)[5]),  "=r"((r)[6]),  "=r"((r)[7]),         \
          "=r"((r)[8]),  "=r"((r)[9]),  "=r"((r)[10]), "=r"((r)[11]),        \
          "=r"((r)[12]), "=r"((r)[13]), "=r"((r)[14]), "=r"((r)[15]),        \
          "=r"((r)[16]), "=r"((r)[17]), "=r"((r)[18]), "=r"((r)[19]),        \
          "=r"((r)[20]), "=r"((r)[21]), "=r"((r)[22]), "=r"((r)[23]),        \
          "=r"((r)[24]), "=r"((r)[25]), "=r"((r)[26]), "=r"((r)[27]),        \
          "=r"((r)[28]), "=r"((r)[29]), "=r"((r)[30]), "=r"((r)[31])         \
        : "r"(ta))

#if TC_OK
// SS MMA, cta_group::1, kind::f16 (bf16 via idesc), fp32 accumulate
__device__ __forceinline__ void mma_bf16_ss(uint32_t d, uint64_t ad, uint64_t bd,
                                            uint32_t idesc, uint32_t en) {
    asm volatile(
        "{\n\t.reg .pred p;\n\tsetp.ne.u32 p, %5, 0;\n\t"
        "tcgen05.mma.cta_group::1.kind::f16 [%0], %1, %2, %3, {%4, %4, %4, %4}, p;\n\t}"
        :: "r"(d), "l"(ad), "l"(bd), "r"(idesc), "r"(0u), "r"(en) : "memory");
}
#endif

// SW128 smem descriptor (layout=2, version=1, SBO=64, LBO=1)
__device__ __forceinline__ uint64_t smem_desc(uint32_t addr) {
    const uint64_t base = (uint64_t(2) << 61) | (uint64_t(1) << 46)
                        | (uint64_t(64) << 32) | (uint64_t(1) << 16);
    return base | ((uint64_t)(addr >> 4) & 0x3FFF);
}

// idesc: dtype F32, atype/btype BF16, N=128, M=128
#define TC_IDESC ((1u<<4) | (1u<<7) | (1u<<10) | ((128u/8u)<<17) | ((128u/16u)<<24))

// blocked-atom SW128 byte offset for (row, col) in a 128x128 bf16 tile
__device__ __forceinline__ int tile_off(int row, int col) {
    int atom = (row >> 3) + (col >> 6) * 16;
    int off  = atom * 1024 + (row & 7) * 128 + (col & 63) * 2;
    return off ^ ((off >> 3) & 0x70);
}

__device__ __forceinline__ ull pack4h(__nv_bfloat16 a, __nv_bfloat16 b,
                                      __nv_bfloat16 c, __nv_bfloat16 d) {
    return (ull)__bfloat16_as_ushort(a) | ((ull)__bfloat16_as_ushort(b) << 16)
         | ((ull)__bfloat16_as_ushort(c) << 32) | ((ull)__bfloat16_as_ushort(d) << 48);
}

// ---------------- weight pack: fp32 [Kfull,Nfull] -> swizzled bf16 hi/lo tiles --
__global__ void pack_w(const float* __restrict__ src, __nv_bfloat16* __restrict__ dh,
                       __nv_bfloat16* __restrict__ dl, int Kfull, int Nfull)
{
    int idx = blockIdx.x * 256 + threadIdx.x;
    int kchunks = Kfull >> 7;
    int block  = idx >> 14;
    int within = idx & 16383;
    int k = within & 127;
    int n = within >> 7;
    int nt = block / kchunks;
    int kc = block - nt * kchunks;
    float v = src[(size_t)(kc*128 + k) * Nfull + nt*128 + n];
    __nv_bfloat16 h = __float2bfloat16(v);
    __nv_bfloat16 l = __float2bfloat16(v - __bfloat162float(h));
    int di = (block << 14) + (tile_off(n, k) >> 1);
    dh[di] = h; dl[di] = l;
}

// ---------------- pack Wq|Wk|Wv1|Wv2 -> g_wqkv [l][c][512] fp32 ----------------
__global__ void pack_qkv_kernel(const float* __restrict__ Wq, const float* __restrict__ Wk,
                                const float* __restrict__ Wv1, const float* __restrict__ Wv2)
{
    int idx = blockIdx.x * 256 + threadIdx.x;
    int l = idx >> 16;
    int c = (idx >> 9) & 127;
    int n = idx & 511;
    int col = n & 127;
    const float* src;
    switch (n >> 7) {
        case 0:  src = Wq;  break;
        case 1:  src = Wk;  break;
        case 2:  src = Wv1; break;
        default: src = Wv2; break;
    }
    g_wqkv[idx] = src[((size_t)l*Dd + c)*Dd + col];
}

// ---------------- tensor-core GEMM: C[128 tile x 128 tile] -----------------
#define SM_AHI 1024
#define SM_ALO (1024 + 32768)
#define SM_WHI (1024 + 65536)
#define SM_WLO (1024 + 98304)
#define SMEM_BYTES (1024 + 131072)

template<bool RELU, bool RESID, bool LN>
__global__ void __launch_bounds__(128)
tc_gemm(const float* __restrict__ A,
        const __nv_bfloat16* __restrict__ Whi, const __nv_bfloat16* __restrict__ Wlo,
        const float* __restrict__ bias, const float* __restrict__ resid,
        const float* __restrict__ lng,  const float* __restrict__ lnb,
        float* __restrict__ C, int K, int N)
{
    extern __shared__ char smem[];
    const int t = threadIdx.x;
    const int bm0 = blockIdx.y * 128, bn0 = blockIdx.x * 128;
    const int kchunks = K >> 7;
    float v[128];

#if TC_OK
    uint32_t sb = smem_u32(smem);
    const int wid = t >> 5;

    if (wid == 0) TC_ALLOC(sb, 128);
    if (t == 0)   MBAR_INIT(sb + 8, 1);
    __syncthreads();
    uint32_t tmem;
    asm volatile("ld.shared.b32 %0, [%1];" : "=r"(tmem) : "r"(sb));

    for (int kc = 0; kc < kchunks; kc++) {
        if (kc > 0) { MBAR_WAIT(sb + 8, (kc - 1) & 1); }   // prev chunk MMAs done
        // ---- copy pre-swizzled W chunk (hi+lo, 32KB each) ----
        {
            const uint4* srcH = (const uint4*)(Whi + (size_t)(blockIdx.x*kchunks + kc) * 16384);
            const uint4* srcL = (const uint4*)(Wlo + (size_t)(blockIdx.x*kchunks + kc) * 16384);
            uint4* dH = (uint4*)(smem + SM_WHI);
            uint4* dL = (uint4*)(smem + SM_WLO);
#pragma unroll
            for (int i = 0; i < 16; i++) {
                dH[t + i*128] = srcH[t + i*128];
                dL[t + i*128] = srcL[t + i*128];
            }
        }
        // ---- convert A chunk fp32 -> bf16 hi/lo, swizzled ----
#pragma unroll 4
        for (int i = 0; i < 32; i++) {
            int f   = i*128 + t;          // float4 id, coalesced
            int row = f >> 5;
            int c4  = (f & 31) * 4;
            float4 av = *(const float4*)(A + (size_t)(bm0 + row)*K + kc*128 + c4);
            __nv_bfloat16 h0 = __float2bfloat16(av.x), h1 = __float2bfloat16(av.y);
            __nv_bfloat16 h2 = __float2bfloat16(av.z), h3 = __float2bfloat16(av.w);
            __nv_bfloat16 l0 = __float2bfloat16(av.x - __bfloat162float(h0));
            __nv_bfloat16 l1 = __float2bfloat16(av.y - __bfloat162float(h1));
            __nv_bfloat16 l2 = __float2bfloat16(av.z - __bfloat162float(h2));
            __nv_bfloat16 l3 = __float2bfloat16(av.w - __bfloat162float(h3));
            int sw = tile_off(row, c4);
            *(ull*)(smem + SM_AHI + sw) = pack4h(h0, h1, h2, h3);
            *(ull*)(smem + SM_ALO + sw) = pack4h(l0, l1, l2, l3);
        }
        FENCE_ASYNC();
        __syncthreads();
        // ---- MMAs: D += Ah*Wh + Ah*Wl + Al*Wh over 8 K-steps of 16 ----
        if (wid == 0 && elect_one()) {
            uint64_t ah = smem_desc(sb + SM_AHI), al = smem_desc(sb + SM_ALO);
            uint64_t wh = smem_desc(sb + SM_WHI), wl = smem_desc(sb + SM_WLO);
#pragma unroll
            for (int ks = 0; ks < 8; ks++) {
                uint64_t off = (uint64_t)((ks >> 2) * 1024 + (ks & 3) * 2);
                mma_bf16_ss(tmem, ah + off, wh + off, TC_IDESC, (kc == 0 && ks == 0) ? 0u : 1u);
                mma_bf16_ss(tmem, ah + off, wl + off, TC_IDESC, 1u);
                mma_bf16_ss(tmem, al + off, wh + off, TC_IDESC, 1u);
            }
            TC_COMMIT(sb + 8);
        }
    }
    MBAR_WAIT(sb + 8, (kchunks - 1) & 1);
    TC_FENCE_AFTER();
    __syncthreads();

    // ---- read D from TMEM: lane owns full row (row == bm0 + t) ----
    {
        uint32_t tmp[32];
#pragma unroll
        for (int c = 0; c < 4; c++) {
            TC_LD_X32(tmp, tmem + c * 32);
            TC_WAIT_LD();
#pragma unroll
            for (int j = 0; j < 32; j++) v[c*32 + j] = __uint_as_float(tmp[j]);
        }
    }
    TC_FENCE_BEFORE();
    __syncthreads();
    if (t == 0) MBAR_INVAL(sb + 8);
    if (wid == 0) TC_DEALLOC(tmem, 128);

#else
    // ---------- SIMT fallback (compute_103 PTX pass; correct, not fast) ----------
    for (int j = 0; j < 128; j++) v[j] = 0.f;
    float* sA = (float*)(smem + 1024);                  // [128][129] fp32
    float* sW = (float*)(smem + 1024 + 128*129*4);      // [128][33]  fp32 (32-col block)
    for (int kc = 0; kc < kchunks; kc++) {
        __syncthreads();
        for (int i = 0; i < 128; i++)
            sA[i*129 + t] = A[(size_t)(bm0 + i)*K + kc*128 + t];
        __syncthreads();
        const __nv_bfloat16* bh = Whi + (size_t)(blockIdx.x*kchunks + kc) * 16384;
        const __nv_bfloat16* bl = Wlo + (size_t)(blockIdx.x*kchunks + kc) * 16384;
        for (int jb = 0; jb < 4; jb++) {
            for (int e = 0; e < 32; e++) {
                int id = e*128 + t;
                int k = id >> 5, jl = id & 31;
                int off = tile_off(jb*32 + jl, k) >> 1;
                sW[k*33 + jl] = __bfloat162float(bh[off]) + __bfloat162float(bl[off]);
            }
            __syncthreads();
            for (int k = 0; k < 128; k++) {
                float a = sA[t*129 + k];
                for (int jl = 0; jl < 32; jl++)
                    v[jb*32 + jl] += a * sW[k*33 + jl];
            }
            __syncthreads();
        }
    }
#endif

    // ---- stage epilogue vectors in (now free) smem ----
    __syncthreads();
    float* sBias = (float*)(smem + 1024);
    float* sG    = sBias + 128;
    float* sB2   = sBias + 256;
    sBias[t] = bias ? bias[bn0 + t] : 0.f;
    if (LN) { sG[t] = lng[bn0 + t]; sB2[t] = lnb[bn0 + t]; }
    __syncthreads();

    const int row = bm0 + t;
    if (RESID) {
#pragma unroll 8
        for (int j4 = 0; j4 < 32; j4++) {
            float4 r = *(const float4*)(resid + (size_t)row*N + bn0 + j4*4);
            v[j4*4+0] += sBias[j4*4+0] + r.x;
            v[j4*4+1] += sBias[j4*4+1] + r.y;
            v[j4*4+2] += sBias[j4*4+2] + r.z;
            v[j4*4+3] += sBias[j4*4+3] + r.w;
        }
    } else {
#pragma unroll
        for (int j = 0; j < 128; j++) v[j] += sBias[j];
    }
    if (RELU) {
#pragma unroll
        for (int j = 0; j < 128; j++) v[j] = fmaxf(v[j], 0.f);
    }
    if (LN) {
        float s1 = 0.f, s2 = 0.f;
#pragma unroll
        for (int j = 0; j < 128; j++) { s1 += v[j]; s2 += v[j]*v[j]; }
        float mean = s1 * (1.f/128.f);
        float var  = s2 * (1.f/128.f) - mean*mean;
        float rstd = rsqrtf(var + 1e-5f);
#pragma unroll
        for (int j = 0; j < 128; j++)
            v[j] = (v[j] - mean) * rstd * sG[j] + sB2[j];
    }
#pragma unroll 8
    for (int j4 = 0; j4 < 32; j4++)
        *(float4*)(C + (size_t)row*N + bn0 + j4*4) =
            make_float4(v[j4*4+0], v[j4*4+1], v[j4*4+2], v[j4*4+3]);
}

// ---------------- embedding ----------------
__global__ void embed_kernel(const float* __restrict__ x,
                             const float* __restrict__ ea,
                             const unsigned int* __restrict__ mask,
                             const float* __restrict__ nW, const float* __restrict__ nb,
                             const float* __restrict__ eW, const float* __restrict__ eb,
                             const float* __restrict__ noe)
{
    int tkn = blockIdx.x;
    int b   = tkn >> 12;
    int ij  = tkn & 4095;
    int i   = ij >> 6, j = ij & 63;
    int d   = threadIdx.x;
    __shared__ float s_in[16];
    float out;
    if (i == j) {
        if (d < 16) s_in[d] = x[(b*Nn + i)*16 + d];
        __syncthreads();
        float acc = nb[d];
#pragma unroll
        for (int c = 0; c < 16; c++) acc += s_in[c] * nW[c*Dd + d];
        out = acc;
    } else {
        if (d < 8) s_in[d] = ea[tkn*8 + d];
        __syncthreads();
        if (mask[tkn] != 0u) {
            float acc = eb[d];
#pragma unroll
            for (int c = 0; c < 8; c++) acc += s_in[c] * eW[c*Dd + d];
            out = acc;
        } else {
            out = noe[d];
        }
    }
    g_tok[tkn*Dd + d] = out;
}

// ---------------- attention scores ----------------
__global__ void __launch_bounds__(256) attn_s_kernel()
{
    const int l = blockIdx.x, h = blockIdx.y, b = blockIdx.z;
    __shared__ float Qs[32][64];
    __shared__ float Ks[32][64];
    const int t = threadIdx.x;
    {
        int r  = t >> 2;
        int dq = (t & 3) * 8;
        const float* qp = g_qkv + ((size_t)((b*Nn + r)*Nn + l))*QKVW + h*DHc + dq;
        const float* kp = g_qkv + ((size_t)((b*Nn + l)*Nn + r))*QKVW + 128 + h*DHc + dq;
        float4 q0 = *(const float4*)qp, q1 = *(const float4*)(qp+4);
        float4 k0 = *(const float4*)kp, k1 = *(const float4*)(kp+4);
        Qs[dq+0][r]=q0.x; Qs[dq+1][r]=q0.y; Qs[dq+2][r]=q0.z; Qs[dq+3][r]=q0.w;
        Qs[dq+4][r]=q1.x; Qs[dq+5][r]=q1.y; Qs[dq+6][r]=q1.z; Qs[dq+7][r]=q1.w;
        Ks[dq+0][r]=k0.x; Ks[dq+1][r]=k0.y; Ks[dq+2][r]=k0.z; Ks[dq+3][r]=k0.w;
        Ks[dq+4][r]=k1.x; Ks[dq+5][r]=k1.y; Ks[dq+6][r]=k1.z; Ks[dq+7][r]=k1.w;
    }
    __syncthreads();
    const int tx = t & 15, ty = t >> 4;
    float acc[4][4];
#pragma unroll
    for (int i = 0; i < 4; i++)
#pragma unroll
        for (int j = 0; j < 4; j++) acc[i][j] = 0.f;
#pragma unroll
    for (int d = 0; d < 32; d++) {
        float4 a = *(const float4*)&Qs[d][ty*4];
        float4 c = *(const float4*)&Ks[d][tx*4];
        float av[4] = {a.x,a.y,a.z,a.w};
        float cv[4] = {c.x,c.y,c.z,c.w};
#pragma unroll
        for (int i = 0; i < 4; i++)
#pragma unroll
            for (int j = 0; j < 4; j++)
                acc[i][j] += av[i]*cv[j];
    }
    float* sp = g_s + ((size_t)((b*Hh + h)*Nn + l)) * 4096;
#pragma unroll
    for (int i = 0; i < 4; i++) {
        *(float4*)&sp[(ty*4 + i)*64 + tx*4] =
            make_float4(acc[i][0]*SCALE_INV, acc[i][1]*SCALE_INV,
                        acc[i][2]*SCALE_INV, acc[i][3]*SCALE_INV);
    }
}

// ---------------- softmax + o = sum_l a * (v1 ⊙ v2) ----------------
__global__ void __launch_bounds__(256) attn_ao_kernel()
{
    const int i = blockIdx.x, h = blockIdx.y, b = blockIdx.z;
    __shared__ float Aa[64][64];
    __shared__ float V1s[64][32];
    __shared__ float redA[4][64];
    __shared__ float redB[4][64];
    const int t = threadIdx.x;
    {
        const int j = t & 63, g = t >> 6;
        const float* sp = g_s + ((size_t)(b*Hh + h)*Nn) * 4096 + i*64 + j;
        float sv[16];
#pragma unroll
        for (int u = 0; u < 16; u++) sv[u] = sp[(size_t)(g*16 + u) * 4096];
        float m = sv[0];
#pragma unroll
        for (int u = 1; u < 16; u++) m = fmaxf(m, sv[u]);
        redA[g][j] = m;
        __syncthreads();
        float cm = fmaxf(fmaxf(redA[0][j], redA[1][j]), fmaxf(redA[2][j], redA[3][j]));
        float lsum = 0.f;
#pragma unroll
        for (int u = 0; u < 16; u++) { sv[u] = __expf(sv[u] - cm); lsum += sv[u]; }
        redB[g][j] = lsum;
        __syncthreads();
        float inv = 1.f / (redB[0][j] + redB[1][j] + redB[2][j] + redB[3][j]);
#pragma unroll
        for (int u = 0; u < 16; u++) Aa[g*16 + u][j] = sv[u] * inv;
    }
    {
        int l  = t >> 2;
        int dq = (t & 3) * 8;
        const float* vp = g_qkv + ((size_t)((b*Nn + i)*Nn + l))*QKVW + 256 + h*DHc + dq;
        *(float4*)&V1s[l][dq]   = *(const float4*)vp;
        *(float4*)&V1s[l][dq+4] = *(const float4*)(vp + 4);
    }
    __syncthreads();

    const int jj = t >> 2;
    const int dq = (t & 3) * 8;
    float acc[8];
#pragma unroll
    for (int u = 0; u < 8; u++) acc[u] = 0.f;
    const float* v2base = g_qkv + ((size_t)(b*Nn)*Nn + jj)*QKVW + 384 + h*DHc + dq;
#pragma unroll 4
    for (int l = 0; l < 64; l++) {
        float av = Aa[l][jj];
        float4 w0 = *(const float4*)&V1s[l][dq];
        float4 w1 = *(const float4*)&V1s[l][dq+4];
        float4 u0 = *(const float4*)(v2base + (size_t)l*Nn*QKVW);
        float4 u1 = *(const float4*)(v2base + (size_t)l*Nn*QKVW + 4);
        acc[0] += av * (w0.x * u0.x);
        acc[1] += av * (w0.y * u0.y);
        acc[2] += av * (w0.z * u0.z);
        acc[3] += av * (w0.w * u0.w);
        acc[4] += av * (w1.x * u1.x);
        acc[5] += av * (w1.y * u1.y);
        acc[6] += av * (w1.z * u1.z);
        acc[7] += av * (w1.w * u1.w);
    }
    float* op = g_o + ((size_t)((b*Nn + i)*Nn + jj))*Dd + h*DHc + dq;
    *(float4*)op       = make_float4(acc[0],acc[1],acc[2],acc[3]);
    *(float4*)(op + 4) = make_float4(acc[4],acc[5],acc[6],acc[7]);
}

// ---------------- final readout ----------------
__global__ void out_kernel(const float* __restrict__ Wout,
                           const float* __restrict__ bout,
                           float* __restrict__ out)
{
    int w    = (blockIdx.x * blockDim.x + threadIdx.x) >> 5;
    int lane = threadIdx.x & 31;
    if (w >= Bc*Nn) return;
    int b = w >> 6, n = w & 63;
    const float* tp = g_tok + ((size_t)((b*Nn + n)*Nn + n)) * Dd;
    float4 tv = *(const float4*)(tp + lane*4);
    float4 wv = *(const float4*)(Wout + lane*4);
    float s = tv.x*wv.x + tv.y*wv.y + tv.z*wv.z + tv.w*wv.w;
#pragma unroll
    for (int m = 16; m > 0; m >>= 1) s += __shfl_xor_sync(0xffffffffu, s, m);
    if (lane == 0) out[w] = s + bout[0];
}

// ---------------- host launcher ----------------
extern "C" void kernel_launch(void* const* d_in, const int* in_sizes, int n_in,
                              void* d_out, int out_size)
{
    const float*        x        = (const float*)d_in[0];
    const float*        ea       = (const float*)d_in[1];
    const unsigned int* mask     = (const unsigned int*)d_in[2];
    const float*        node_W   = (const float*)d_in[3];
    const float*        node_b   = (const float*)d_in[4];
    const float*        edge_W   = (const float*)d_in[5];
    const float*        edge_b   = (const float*)d_in[6];
    const float*        no_edge  = (const float*)d_in[7];
    const float*        Wq       = (const float*)d_in[8];
    const float*        Wk       = (const float*)d_in[9];
    const float*        Wv1      = (const float*)d_in[10];
    const float*        Wv2      = (const float*)d_in[11];
    const float*        Wo       = (const float*)d_in[12];
    const float*        bo       = (const float*)d_in[13];
    const float*        ln1g     = (const float*)d_in[14];
    const float*        ln1b     = (const float*)d_in[15];
    const float*        W1       = (const float*)d_in[16];
    const float*        b1       = (const float*)d_in[17];
    const float*        W2       = (const float*)d_in[18];
    const float*        b2       = (const float*)d_in[19];
    const float*        ln2g     = (const float*)d_in[20];
    const float*        ln2b     = (const float*)d_in[21];
    const float*        Wout     = (const float*)d_in[22];
    const float*        bout     = (const float*)d_in[23];

    float *tok, *qkv, *o, *hid, *wqkv;
    __nv_bfloat16 *whq, *wlq, *who, *wlo_, *wh1, *wl1, *wh2, *wl2;
    cudaGetSymbolAddress((void**)&tok,  g_tok);
    cudaGetSymbolAddress((void**)&qkv,  g_qkv);
    cudaGetSymbolAddress((void**)&o,    g_o);
    cudaGetSymbolAddress((void**)&hid,  g_hid);
    cudaGetSymbolAddress((void**)&wqkv, g_wqkv);
    cudaGetSymbolAddress((void**)&whq,  g_wh_qkv);
    cudaGetSymbolAddress((void**)&wlq,  g_wl_qkv);
    cudaGetSymbolAddress((void**)&who,  g_wh_wo);
    cudaGetSymbolAddress((void**)&wlo_, g_wl_wo);
    cudaGetSymbolAddress((void**)&wh1,  g_wh_w1);
    cudaGetSymbolAddress((void**)&wl1,  g_wl_w1);
    cudaGetSymbolAddress((void**)&wh2,  g_wh_w2);
    cudaGetSymbolAddress((void**)&wl2,  g_wl_w2);

    cudaFuncSetAttribute(tc_gemm<false,false,false>, cudaFuncAttributeMaxDynamicSharedMemorySize, SMEM_BYTES);
    cudaFuncSetAttribute(tc_gemm<true,false,false>,  cudaFuncAttributeMaxDynamicSharedMemorySize, SMEM_BYTES);
    cudaFuncSetAttribute(tc_gemm<false,true,true>,   cudaFuncAttributeMaxDynamicSharedMemorySize, SMEM_BYTES);

    // weight preprocessing
    pack_qkv_kernel<<<(Lc*Dd*QKVW)/256, 256>>>(Wq, Wk, Wv1, Wv2);
    for (int l = 0; l < Lc; l++) {
        pack_w<<<256, 256>>>(wqkv + (size_t)l*65536, whq + (size_t)l*65536, wlq + (size_t)l*65536, 128, 512);
        pack_w<<<64,  256>>>(Wo   + (size_t)l*16384, who + (size_t)l*16384, wlo_ + (size_t)l*16384, 128, 128);
        pack_w<<<256, 256>>>(W1   + (size_t)l*65536, wh1 + (size_t)l*65536, wl1 + (size_t)l*65536, 128, 512);
        pack_w<<<256, 256>>>(W2   + (size_t)l*65536, wh2 + (size_t)l*65536, wl2 + (size_t)l*65536, 512, 128);
    }

    embed_kernel<<<TOK, 128>>>(x, ea, mask, node_W, node_b, edge_W, edge_b, no_edge);

    const dim3 gN1(1, TOK/128);
    const dim3 gN4(4, TOK/128);
    const dim3 ga(Nn, Hh, Bc);

    for (int l = 0; l < Lc; l++) {
        size_t tOff  = (size_t)l * 65536;
        size_t oOff  = (size_t)l * 16384;
        size_t bOff  = (size_t)l * Dd;
        size_t b1Off = (size_t)l * FFc;

        // fused QKV: [TOK,128] @ [128,512]
        tc_gemm<false,false,false><<<gN4, 128, SMEM_BYTES>>>(
            tok, whq + tOff, wlq + tOff, nullptr, nullptr, nullptr, nullptr, qkv, 128, 512);

        attn_s_kernel <<<ga, 256>>>();
        attn_ao_kernel<<<ga, 256>>>();

        // tok = LN(tok + o @ Wo + bo)
        tc_gemm<false,true,true><<<gN1, 128, SMEM_BYTES>>>(
            o, who + oOff, wlo_ + oOff, bo + bOff, tok, ln1g + bOff, ln1b + bOff, tok, 128, 128);
        // hid = relu(tok @ W1 + b1)
        tc_gemm<true,false,false><<<gN4, 128, SMEM_BYTES>>>(
            tok, wh1 + tOff, wl1 + tOff, b1 + b1Off, nullptr, nullptr, nullptr, hid, 128, 512);
        // tok = LN(tok + hid @ W2 + b2)
        tc_gemm<false,true,true><<<gN1, 128, SMEM_BYTES>>>(
            hid, wh2 + tOff, wl2 + tOff, b2 + bOff, tok, ln2g + bOff, ln2b + bOff, tok, 512, 128);
    }

    out_kernel<<<(Bc*Nn*32 + 255)/256, 256>>>(Wout, bout, (float*)d_out);
}

// round 15
// speedup vs baseline: 1.9116x; 1.4449x over previous
#include <cuda_runtime.h>
#include <cuda_bf16.h>
#include <math.h>
#include <stdint.h>

// ---------------- problem constants ----------------
#define Bc   8
#define Nn   64
#define Dd   128
#define Hh   4
#define DHc  32
#define FFc  512
#define Lc   3
#define TOK  (Bc*Nn*Nn)              // 32768 tokens
#define QKVW 512
#define SCALE_INV 0.17677669529663687f

typedef unsigned long long ull;

// tcgen05 only in arch-specific passes (sm_103a cubin); compute_103 PTX gets fallback.
#if defined(__CUDA_ARCH__) && (defined(__CUDA_ARCH_FEAT_SM103_ALL) || \
    defined(__CUDA_ARCH_FEAT_SM100_ALL) || defined(__CUDA_ARCH_SPECIFIC__) || \
    defined(__CUDA_ARCH_FAMILY_SPECIFIC__))
#define TC_OK 1
#else
#define TC_OK 0
#endif

// ---------------- device scratch ----------------
__device__ float g_tok [TOK*Dd];
__device__ float g_qkv [TOK*QKVW];
__device__ float g_s   [Bc*Hh*Nn*Nn*Nn];
__device__ float g_o   [TOK*Dd];
__device__ float g_hid [TOK*FFc];
// packed bf16 hi/lo weights, swizzled blocked-atom tiles of 128x128 (16384 el)
__device__ __nv_bfloat16 g_wh_qkv[Lc*4*16384], g_wl_qkv[Lc*4*16384];
__device__ __nv_bfloat16 g_wh_wo [Lc*1*16384], g_wl_wo [Lc*1*16384];
__device__ __nv_bfloat16 g_wh_w1 [Lc*4*16384], g_wl_w1 [Lc*4*16384];
__device__ __nv_bfloat16 g_wh_w2 [Lc*4*16384], g_wl_w2 [Lc*4*16384];

// ---------------- tcgen05 helpers ----------------
__device__ __forceinline__ uint32_t smem_u32(const void* p) {
    uint32_t a;
    asm("{ .reg .u64 t; cvta.to.shared.u64 t, %1; cvt.u32.u64 %0, t; }" : "=r"(a) : "l"(p));
    return a;
}
__device__ __forceinline__ uint32_t elect_one() {
    uint32_t pred;
    asm volatile("{\n\t.reg .pred p;\n\telect.sync _|p, 0xFFFFFFFF;\n\tselp.b32 %0, 1, 0, p;\n\t}" : "=r"(pred));
    return pred;
}
#define TC_ALLOC(sa, n)   asm volatile("tcgen05.alloc.cta_group::1.sync.aligned.shared::cta.b32 [%0], %1;" :: "r"((uint32_t)(sa)), "r"((uint32_t)(n)) : "memory")
#define TC_DEALLOC(ta, n) asm volatile("tcgen05.dealloc.cta_group::1.sync.aligned.b32 %0, %1;" :: "r"(ta), "r"((uint32_t)(n)))
#define TC_COMMIT(mb)     asm volatile("tcgen05.commit.cta_group::1.mbarrier::arrive::one.shared::cluster.b64 [%0];" :: "r"((uint32_t)(mb)) : "memory")
#define TC_FENCE_AFTER()  asm volatile("tcgen05.fence::after_thread_sync;" ::: "memory")
#define TC_FENCE_BEFORE() asm volatile("tcgen05.fence::before_thread_sync;" ::: "memory")
#define TC_WAIT_LD()      asm volatile("tcgen05.wait::ld.sync.aligned;" ::: "memory")
#define FENCE_ASYNC()     asm volatile("fence.proxy.async.shared::cta;" ::: "memory")
#define MBAR_INIT(mb, c)  asm volatile("mbarrier.init.shared.b64 [%0], %1;" :: "r"((uint32_t)(mb)), "r"((uint32_t)(c)) : "memory")
#define MBAR_INVAL(mb)    asm volatile("mbarrier.inval.shared.b64 [%0];" :: "r"((uint32_t)(mb)) : "memory")

#define MBAR_WAIT(mb, par) do {                                              \
    uint32_t _mb = (uint32_t)(mb), _p = (uint32_t)(par), _done;              \
    asm volatile("{\n\t.reg .pred p;\n\t"                                    \
        "mbarrier.try_wait.parity.acquire.cta.shared::cta.b64 p, [%1], %2;\n\t" \
        "selp.b32 %0, 1, 0, p;\n\t}" : "=r"(_done) : "r"(_mb), "r"(_p) : "memory"); \
    if (!_done) {                                                            \
        asm volatile("{\n\t.reg .pred P1;\n\t"                               \
            "WAIT_LOOP_%=:\n\t"                                              \
            "mbarrier.try_wait.parity.acquire.cta.shared::cta.b64 P1, [%0], %1, 0x989680;\n\t" \
            "@P1 bra.uni WAIT_DONE_%=;\n\tbra.uni WAIT_LOOP_%=;\n\t"          \
            "WAIT_DONE_%=:\n\t}" :: "r"(_mb), "r"(_p) : "memory");           \
    }                                                                        \
} while (0)

#define TC_LD_X32(r, ta)                                                     \
    asm volatile("tcgen05.ld.sync.aligned.32x32b.x32.b32 "                   \
        "{%0, %1, %2, %3, %4, %5, %6, %7, "                                  \
        " %8, %9, %10, %11, %12, %13, %14, %15, "                            \
        " %16, %17, %18, %19, %20, %21, %22, %23, "                          \
        " %24, %25, %26, %27, %28, %29, %30, %31}, [%32];"                   \
        : "=r"((r)[0]),  "=r"((r)[1]),  "=r"((r)[2]),  "=r"((r)[3]),         \
          "=r"((r)[4]),  "=r"((r)[5]),  "=r"((r)[6]),  "=r"((r)[7]),         \
          "=r"((r)[8]),  "=r"((r)[9]),  "=r"((r)[10]), "=r"((r)[11]),        \
          "=r"((r)[12]), "=r"((r)[13]), "=r"((r)[14]), "=r"((r)[15]),        \
          "=r"((r)[16]), "=r"((r)[17]), "=r"((r)[18]), "=r"((r)[19]),        \
          "=r"((r)[20]), "=r"((r)[21]), "=r"((r)[22]), "=r"((r)[23]),        \
          "=r"((r)[24]), "=r"((r)[25]), "=r"((r)[26]), "=r"((r)[27]),        \
          "=r"((r)[28]), "=r"((r)[29]), "=r"((r)[30]), "=r"((r)[31])         \
        : "r"(ta))

#if TC_OK
__device__ __forceinline__ void mma_bf16_ss(uint32_t d, uint64_t ad, uint64_t bd,
                                            uint32_t idesc, uint32_t en) {
    asm volatile(
        "{\n\t.reg .pred p;\n\tsetp.ne.u32 p, %5, 0;\n\t"
        "tcgen05.mma.cta_group::1.kind::f16 [%0], %1, %2, %3, {%4, %4, %4, %4}, p;\n\t}"
        :: "r"(d), "l"(ad), "l"(bd), "r"(idesc), "r"(0u), "r"(en) : "memory");
}
#endif

// SW128 smem descriptor (layout=2, version=1, SBO=64, LBO=1)
__device__ __forceinline__ uint64_t smem_desc(uint32_t addr) {
    const uint64_t base = (uint64_t(2) << 61) | (uint64_t(1) << 46)
                        | (uint64_t(64) << 32) | (uint64_t(1) << 16);
    return base | ((uint64_t)(addr >> 4) & 0x3FFF);
}

// idesc: dtype F32, atype/btype BF16, N=128, M=128 (validated R11)
#define TC_IDESC ((1u<<4) | (1u<<7) | (1u<<10) | ((128u/8u)<<17) | ((128u/16u)<<24))

// blocked-atom SW128 byte offset for (row, col) in a 128x128 bf16 tile (validated R11)
__device__ __forceinline__ int tile_off(int row, int col) {
    int atom = (row >> 3) + (col >> 6) * 16;
    int off  = atom * 1024 + (row & 7) * 128 + (col & 63) * 2;
    return off ^ ((off >> 3) & 0x70);
}

__device__ __forceinline__ ull pack4h(__nv_bfloat16 a, __nv_bfloat16 b,
                                      __nv_bfloat16 c, __nv_bfloat16 d) {
    return (ull)__bfloat16_as_ushort(a) | ((ull)__bfloat16_as_ushort(b) << 16)
         | ((ull)__bfloat16_as_ushort(c) << 32) | ((ull)__bfloat16_as_ushort(d) << 48);
}

// ---------------- single fused weight-pack kernel ----------------
// 13 tiles per layer: [0..3] QKV (Wq|Wk|Wv1|Wv2), [4] Wo, [5..8] W1 n-tiles, [9..12] W2 k-chunks
__global__ void pack_all(const float* __restrict__ Wq, const float* __restrict__ Wk,
                         const float* __restrict__ Wv1, const float* __restrict__ Wv2,
                         const float* __restrict__ Wo, const float* __restrict__ W1,
                         const float* __restrict__ W2)
{
    int idx = blockIdx.x * 256 + threadIdx.x;   // over Lc*13*16384
    int tile   = idx >> 14;
    int within = idx & 16383;
    int k = within & 127;       // K index inside tile
    int n = within >> 7;        // N index inside tile
    int l = tile / 13, u = tile - l * 13;

    float v;
    __nv_bfloat16 *dh, *dl;
    size_t dbase;
    if (u < 4) {
        const float* s = (u == 0) ? Wq : (u == 1) ? Wk : (u == 2) ? Wv1 : Wv2;
        v = s[(size_t)l*16384 + k*128 + n];
        dh = g_wh_qkv; dl = g_wl_qkv; dbase = (size_t)(l*4 + u) * 16384;
    } else if (u == 4) {
        v = Wo[(size_t)l*16384 + k*128 + n];
        dh = g_wh_wo; dl = g_wl_wo; dbase = (size_t)l * 16384;
    } else if (u < 9) {
        int nt = u - 5;
        v = W1[(size_t)l*65536 + (size_t)k*512 + nt*128 + n];
        dh = g_wh_w1; dl = g_wl_w1; dbase = (size_t)(l*4 + nt) * 16384;
    } else {
        int kc = u - 9;
        v = W2[(size_t)l*65536 + (size_t)(kc*128 + k)*128 + n];
        dh = g_wh_w2; dl = g_wl_w2; dbase = (size_t)(l*4 + kc) * 16384;
    }
    __nv_bfloat16 h  = __float2bfloat16(v);
    __nv_bfloat16 lo = __float2bfloat16(v - __bfloat162float(h));
    size_t di = dbase + (size_t)(tile_off(n, k) >> 1);
    dh[di] = h; dl[di] = lo;
}

// ---------------- tensor-core GEMM: one CTA = 128 rows x NT*128 cols -----------
// smem: [0]=tmem ptr, [8],[16]=mbarriers; A hi/lo 32KB each; W double-buffered hi/lo.
#define SM_AH  1024
#define SM_AL  (1024 + 32768)
#define SM_W   (1024 + 65536)         // + buf*65536 ; hi at +0, lo at +32768
#define SMEM_BYTES (1024 + 65536 + 2*65536)   // 197632

template<int NT, bool RELU, bool RESID, bool LN>
__global__ void __launch_bounds__(256)
tc_gemm(const float* __restrict__ A,
        const __nv_bfloat16* __restrict__ Whi, const __nv_bfloat16* __restrict__ Wlo,
        const float* __restrict__ bias, const float* __restrict__ resid,
        const float* __restrict__ lng,  const float* __restrict__ lnb,
        float* __restrict__ C, int K)
{
    const int N = NT * 128;
    extern __shared__ char smem[];
    const int t = threadIdx.x, wid = t >> 5, lid = t & 31;
    const int bm0 = blockIdx.x * 128;
    const int kchunks = K >> 7;
    const int wg  = wid >> 2;             // column half (0: cols 0-63, 1: 64-127 of tile)
    const int row = (wid & 3) * 32 + lid; // local row 0..127
    float v[64];

#if TC_OK
    uint32_t sb = smem_u32(smem);
    if (wid == 0) TC_ALLOC(sb, 512);
    if (t == 0) { MBAR_INIT(sb + 8, 1); MBAR_INIT(sb + 16, 1); }
    __syncthreads();
    uint32_t tmem;
    asm volatile("ld.shared.b32 %0, [%1];" : "=r"(tmem) : "r"(sb));

    int done = 0;   // completed MMA steps observed (step s -> mbar s&1, parity (s>>1)&1)
#define WAIT_UNTIL(target) do { \
        while (done < (target)) { MBAR_WAIT(sb + 8 + (done & 1) * 8, (done >> 1) & 1); done++; } \
    } while (0)

    for (int kc = 0; kc < kchunks; kc++) {
        WAIT_UNTIL(kc * NT);   // all MMAs of previous chunk done before overwriting A
        // ---- convert A chunk fp32 -> bf16 hi/lo, swizzled (256 thr, 16 iters) ----
#pragma unroll 4
        for (int i = 0; i < 16; i++) {
            int f  = i * 256 + t;
            int ar = f >> 5;
            int c4 = (f & 31) * 4;
            float4 av = *(const float4*)(A + (size_t)(bm0 + ar) * K + kc * 128 + c4);
            __nv_bfloat16 h0 = __float2bfloat16(av.x), h1 = __float2bfloat16(av.y);
            __nv_bfloat16 h2 = __float2bfloat16(av.z), h3 = __float2bfloat16(av.w);
            __nv_bfloat16 l0 = __float2bfloat16(av.x - __bfloat162float(h0));
            __nv_bfloat16 l1 = __float2bfloat16(av.y - __bfloat162float(h1));
            __nv_bfloat16 l2 = __float2bfloat16(av.z - __bfloat162float(h2));
            __nv_bfloat16 l3 = __float2bfloat16(av.w - __bfloat162float(h3));
            int sw = tile_off(ar, c4);
            *(ull*)(smem + SM_AH + sw) = pack4h(h0, h1, h2, h3);
            *(ull*)(smem + SM_AL + sw) = pack4h(l0, l1, l2, l3);
        }
#pragma unroll
        for (int nt = 0; nt < NT; nt++) {
            const int step = kc * NT + nt;
            if (step >= 2) WAIT_UNTIL(step - 1);     // W buffer (step&1) free
            // ---- copy pre-swizzled W tile into buffer step&1 ----
            {
                const int wb = (step & 1) * 65536;
                const uint4* srcH = (const uint4*)(Whi + (size_t)(nt * kchunks + kc) * 16384);
                const uint4* srcL = (const uint4*)(Wlo + (size_t)(nt * kchunks + kc) * 16384);
                uint4* dH = (uint4*)(smem + SM_W + wb);
                uint4* dL = (uint4*)(smem + SM_W + wb + 32768);
#pragma unroll
                for (int i = 0; i < 8; i++) {
                    dH[t + i * 256] = srcH[t + i * 256];
                    dL[t + i * 256] = srcL[t + i * 256];
                }
            }
            FENCE_ASYNC();
            __syncthreads();
            // ---- 8 K-steps x (Ah*Wh + Ah*Wl + Al*Wh) into D[nt] ----
            if (wid == 0 && elect_one()) {
                const int wb = (step & 1) * 65536;
                uint64_t ah = smem_desc(sb + SM_AH);
                uint64_t al = smem_desc(sb + SM_AL);
                uint64_t wh = smem_desc(sb + SM_W + wb);
                uint64_t wl = smem_desc(sb + SM_W + wb + 32768);
                uint32_t dD = tmem + nt * 128;
#pragma unroll
                for (int ks = 0; ks < 8; ks++) {
                    uint64_t off = (uint64_t)((ks >> 2) * 1024 + (ks & 3) * 2);
                    mma_bf16_ss(dD, ah + off, wh + off, TC_IDESC, (kc == 0 && ks == 0) ? 0u : 1u);
                    mma_bf16_ss(dD, ah + off, wl + off, TC_IDESC, 1u);
                    mma_bf16_ss(dD, al + off, wh + off, TC_IDESC, 1u);
                }
                TC_COMMIT(sb + 8 + (step & 1) * 8);
            }
        }
    }
    WAIT_UNTIL(kchunks * NT);
#undef WAIT_UNTIL
    TC_FENCE_AFTER();
    __syncthreads();
#endif

    // ---- stage epilogue vectors (A/W smem regions are free now) ----
    float* sB  = (float*)(smem + 1024);   // [512]
    float* sG  = sB + 512;                // [128]
    float* sBt = sG + 128;                // [128]
    float* sS1 = sBt + 128;               // [128][2]
    float* sS2 = sS1 + 256;               // [128][2]
    for (int i = t; i < N; i += 256) sB[i] = bias ? bias[i] : 0.f;
    if (LN && t < 128) { sG[t] = lng[t]; sBt[t] = lnb[t]; }
    __syncthreads();

#pragma unroll
    for (int nt = 0; nt < NT; nt++) {
        const int colbase = nt * 128 + wg * 64;
#if TC_OK
        {
            uint32_t tmp[32];
            TC_LD_X32(tmp, tmem + nt * 128 + wg * 64);
            TC_WAIT_LD();
#pragma unroll
            for (int j = 0; j < 32; j++) v[j] = __uint_as_float(tmp[j]);
            TC_LD_X32(tmp, tmem + nt * 128 + wg * 64 + 32);
            TC_WAIT_LD();
#pragma unroll
            for (int j = 0; j < 32; j++) v[32 + j] = __uint_as_float(tmp[j]);
        }
#else
        // SIMT fallback (compute_103 PTX pass only; correct, not fast)
        for (int j = 0; j < 64; j++) v[j] = 0.f;
        for (int kc = 0; kc < kchunks; kc++) {
            const __nv_bfloat16* bh = Whi + (size_t)(nt * kchunks + kc) * 16384;
            const __nv_bfloat16* bl = Wlo + (size_t)(nt * kchunks + kc) * 16384;
            for (int k = 0; k < 128; k++) {
                float a = A[(size_t)(bm0 + row) * K + kc * 128 + k];
                for (int j = 0; j < 64; j++) {
                    int off = tile_off(wg * 64 + j, k) >> 1;
                    v[j] += a * (__bfloat162float(bh[off]) + __bfloat162float(bl[off]));
                }
            }
        }
#endif
#pragma unroll
        for (int j = 0; j < 64; j++) v[j] += sB[colbase + j];
        if (RESID) {
#pragma unroll
            for (int j4 = 0; j4 < 16; j4++) {
                float4 r = *(const float4*)(resid + (size_t)(bm0 + row) * N + colbase + j4 * 4);
                v[j4*4+0] += r.x; v[j4*4+1] += r.y; v[j4*4+2] += r.z; v[j4*4+3] += r.w;
            }
        }
        if (RELU) {
#pragma unroll
            for (int j = 0; j < 64; j++) v[j] = fmaxf(v[j], 0.f);
        }
        if (LN) {
            float s1 = 0.f, s2 = 0.f;
#pragma unroll
            for (int j = 0; j < 64; j++) { s1 += v[j]; s2 += v[j]*v[j]; }
            sS1[row*2 + wg] = s1; sS2[row*2 + wg] = s2;
            __syncthreads();
            float ts1 = sS1[row*2] + sS1[row*2+1];
            float ts2 = sS2[row*2] + sS2[row*2+1];
            float mean = ts1 * (1.f/128.f);
            float var  = ts2 * (1.f/128.f) - mean*mean;
            float rstd = rsqrtf(var + 1e-5f);
#pragma unroll
            for (int j = 0; j < 64; j++)
                v[j] = (v[j] - mean) * rstd * sG[wg*64 + j] + sBt[wg*64 + j];
        }
#pragma unroll
        for (int j4 = 0; j4 < 16; j4++)
            *(float4*)(C + (size_t)(bm0 + row) * N + colbase + j4 * 4) =
                make_float4(v[j4*4+0], v[j4*4+1], v[j4*4+2], v[j4*4+3]);
    }

#if TC_OK
    TC_FENCE_BEFORE();
    __syncthreads();
    if (t == 0) { MBAR_INVAL(sb + 8); MBAR_INVAL(sb + 16); }
    __syncthreads();
    if (wid == 0) TC_DEALLOC(tmem, 512);
#endif
}

// ---------------- embedding ----------------
__global__ void embed_kernel(const float* __restrict__ x,
                             const float* __restrict__ ea,
                             const unsigned int* __restrict__ mask,
                             const float* __restrict__ nW, const float* __restrict__ nb,
                             const float* __restrict__ eW, const float* __restrict__ eb,
                             const float* __restrict__ noe)
{
    int tkn = blockIdx.x;
    int b   = tkn >> 12;
    int ij  = tkn & 4095;
    int i   = ij >> 6, j = ij & 63;
    int d   = threadIdx.x;
    __shared__ float s_in[16];
    float out;
    if (i == j) {
        if (d < 16) s_in[d] = x[(b*Nn + i)*16 + d];
        __syncthreads();
        float acc = nb[d];
#pragma unroll
        for (int c = 0; c < 16; c++) acc += s_in[c] * nW[c*Dd + d];
        out = acc;
    } else {
        if (d < 8) s_in[d] = ea[tkn*8 + d];
        __syncthreads();
        if (mask[tkn] != 0u) {
            float acc = eb[d];
#pragma unroll
            for (int c = 0; c < 8; c++) acc += s_in[c] * eW[c*Dd + d];
            out = acc;
        } else {
            out = noe[d];
        }
    }
    g_tok[tkn*Dd + d] = out;
}

// ---------------- attention scores ----------------
__global__ void __launch_bounds__(256) attn_s_kernel()
{
    const int l = blockIdx.x, h = blockIdx.y, b = blockIdx.z;
    __shared__ float Qs[32][64];
    __shared__ float Ks[32][64];
    const int t = threadIdx.x;
    {
        int r  = t >> 2;
        int dq = (t & 3) * 8;
        const float* qp = g_qkv + ((size_t)((b*Nn + r)*Nn + l))*QKVW + h*DHc + dq;
        const float* kp = g_qkv + ((size_t)((b*Nn + l)*Nn + r))*QKVW + 128 + h*DHc + dq;
        float4 q0 = *(const float4*)qp, q1 = *(const float4*)(qp+4);
        float4 k0 = *(const float4*)kp, k1 = *(const float4*)(kp+4);
        Qs[dq+0][r]=q0.x; Qs[dq+1][r]=q0.y; Qs[dq+2][r]=q0.z; Qs[dq+3][r]=q0.w;
        Qs[dq+4][r]=q1.x; Qs[dq+5][r]=q1.y; Qs[dq+6][r]=q1.z; Qs[dq+7][r]=q1.w;
        Ks[dq+0][r]=k0.x; Ks[dq+1][r]=k0.y; Ks[dq+2][r]=k0.z; Ks[dq+3][r]=k0.w;
        Ks[dq+4][r]=k1.x; Ks[dq+5][r]=k1.y; Ks[dq+6][r]=k1.z; Ks[dq+7][r]=k1.w;
    }
    __syncthreads();
    const int tx = t & 15, ty = t >> 4;
    float acc[4][4];
#pragma unroll
    for (int i = 0; i < 4; i++)
#pragma unroll
        for (int j = 0; j < 4; j++) acc[i][j] = 0.f;
#pragma unroll
    for (int d = 0; d < 32; d++) {
        float4 a = *(const float4*)&Qs[d][ty*4];
        float4 c = *(const float4*)&Ks[d][tx*4];
        float av[4] = {a.x,a.y,a.z,a.w};
        float cv[4] = {c.x,c.y,c.z,c.w};
#pragma unroll
        for (int i = 0; i < 4; i++)
#pragma unroll
            for (int j = 0; j < 4; j++)
                acc[i][j] += av[i]*cv[j];
    }
    float* sp = g_s + ((size_t)((b*Hh + h)*Nn + l)) * 4096;
#pragma unroll
    for (int i = 0; i < 4; i++) {
        *(float4*)&sp[(ty*4 + i)*64 + tx*4] =
            make_float4(acc[i][0]*SCALE_INV, acc[i][1]*SCALE_INV,
                        acc[i][2]*SCALE_INV, acc[i][3]*SCALE_INV);
    }
}

// ---------------- softmax + o = sum_l a * (v1 ⊙ v2) ----------------
__global__ void __launch_bounds__(256) attn_ao_kernel()
{
    const int i = blockIdx.x, h = blockIdx.y, b = blockIdx.z;
    __shared__ float Aa[64][64];
    __shared__ float V1s[64][32];
    __shared__ float redA[4][64];
    __shared__ float redB[4][64];
    const int t = threadIdx.x;
    {
        const int j = t & 63, g = t >> 6;
        const float* sp = g_s + ((size_t)(b*Hh + h)*Nn) * 4096 + i*64 + j;
        float sv[16];
#pragma unroll
        for (int u = 0; u < 16; u++) sv[u] = sp[(size_t)(g*16 + u) * 4096];
        float m = sv[0];
#pragma unroll
        for (int u = 1; u < 16; u++) m = fmaxf(m, sv[u]);
        redA[g][j] = m;
        __syncthreads();
        float cm = fmaxf(fmaxf(redA[0][j], redA[1][j]), fmaxf(redA[2][j], redA[3][j]));
        float lsum = 0.f;
#pragma unroll
        for (int u = 0; u < 16; u++) { sv[u] = __expf(sv[u] - cm); lsum += sv[u]; }
        redB[g][j] = lsum;
        __syncthreads();
        float inv = 1.f / (redB[0][j] + redB[1][j] + redB[2][j] + redB[3][j]);
#pragma unroll
        for (int u = 0; u < 16; u++) Aa[g*16 + u][j] = sv[u] * inv;
    }
    {
        int l  = t >> 2;
        int dq = (t & 3) * 8;
        const float* vp = g_qkv + ((size_t)((b*Nn + i)*Nn + l))*QKVW + 256 + h*DHc + dq;
        *(float4*)&V1s[l][dq]   = *(const float4*)vp;
        *(float4*)&V1s[l][dq+4] = *(const float4*)(vp + 4);
    }
    __syncthreads();

    const int jj = t >> 2;
    const int dq = (t & 3) * 8;
    float acc[8];
#pragma unroll
    for (int u = 0; u < 8; u++) acc[u] = 0.f;
    const float* v2base = g_qkv + ((size_t)(b*Nn)*Nn + jj)*QKVW + 384 + h*DHc + dq;
#pragma unroll 4
    for (int l = 0; l < 64; l++) {
        float av = Aa[l][jj];
        float4 w0 = *(const float4*)&V1s[l][dq];
        float4 w1 = *(const float4*)&V1s[l][dq+4];
        float4 u0 = *(const float4*)(v2base + (size_t)l*Nn*QKVW);
        float4 u1 = *(const float4*)(v2base + (size_t)l*Nn*QKVW + 4);
        acc[0] += av * (w0.x * u0.x);
        acc[1] += av * (w0.y * u0.y);
        acc[2] += av * (w0.z * u0.z);
        acc[3] += av * (w0.w * u0.w);
        acc[4] += av * (w1.x * u1.x);
        acc[5] += av * (w1.y * u1.y);
        acc[6] += av * (w1.z * u1.z);
        acc[7] += av * (w1.w * u1.w);
    }
    float* op = g_o + ((size_t)((b*Nn + i)*Nn + jj))*Dd + h*DHc + dq;
    *(float4*)op       = make_float4(acc[0],acc[1],acc[2],acc[3]);
    *(float4*)(op + 4) = make_float4(acc[4],acc[5],acc[6],acc[7]);
}

// ---------------- final readout ----------------
__global__ void out_kernel(const float* __restrict__ Wout,
                           const float* __restrict__ bout,
                           float* __restrict__ out)
{
    int w    = (blockIdx.x * blockDim.x + threadIdx.x) >> 5;
    int lane = threadIdx.x & 31;
    if (w >= Bc*Nn) return;
    int b = w >> 6, n = w & 63;
    const float* tp = g_tok + ((size_t)((b*Nn + n)*Nn + n)) * Dd;
    float4 tv = *(const float4*)(tp + lane*4);
    float4 wv = *(const float4*)(Wout + lane*4);
    float s = tv.x*wv.x + tv.y*wv.y + tv.z*wv.z + tv.w*wv.w;
#pragma unroll
    for (int m = 16; m > 0; m >>= 1) s += __shfl_xor_sync(0xffffffffu, s, m);
    if (lane == 0) out[w] = s + bout[0];
}

// ---------------- host launcher ----------------
extern "C" void kernel_launch(void* const* d_in, const int* in_sizes, int n_in,
                              void* d_out, int out_size)
{
    const float*        x        = (const float*)d_in[0];
    const float*        ea       = (const float*)d_in[1];
    const unsigned int* mask     = (const unsigned int*)d_in[2];
    const float*        node_W   = (const float*)d_in[3];
    const float*        node_b   = (const float*)d_in[4];
    const float*        edge_W   = (const float*)d_in[5];
    const float*        edge_b   = (const float*)d_in[6];
    const float*        no_edge  = (const float*)d_in[7];
    const float*        Wq       = (const float*)d_in[8];
    const float*        Wk       = (const float*)d_in[9];
    const float*        Wv1      = (const float*)d_in[10];
    const float*        Wv2      = (const float*)d_in[11];
    const float*        Wo       = (const float*)d_in[12];
    const float*        bo       = (const float*)d_in[13];
    const float*        ln1g     = (const float*)d_in[14];
    const float*        ln1b     = (const float*)d_in[15];
    const float*        W1       = (const float*)d_in[16];
    const float*        b1       = (const float*)d_in[17];
    const float*        W2       = (const float*)d_in[18];
    const float*        b2       = (const float*)d_in[19];
    const float*        ln2g     = (const float*)d_in[20];
    const float*        ln2b     = (const float*)d_in[21];
    const float*        Wout     = (const float*)d_in[22];
    const float*        bout     = (const float*)d_in[23];

    float *tok, *qkv, *o, *hid;
    __nv_bfloat16 *whq, *wlq, *who, *wlo_, *wh1, *wl1, *wh2, *wl2;
    cudaGetSymbolAddress((void**)&tok,  g_tok);
    cudaGetSymbolAddress((void**)&qkv,  g_qkv);
    cudaGetSymbolAddress((void**)&o,    g_o);
    cudaGetSymbolAddress((void**)&hid,  g_hid);
    cudaGetSymbolAddress((void**)&whq,  g_wh_qkv);
    cudaGetSymbolAddress((void**)&wlq,  g_wl_qkv);
    cudaGetSymbolAddress((void**)&who,  g_wh_wo);
    cudaGetSymbolAddress((void**)&wlo_, g_wl_wo);
    cudaGetSymbolAddress((void**)&wh1,  g_wh_w1);
    cudaGetSymbolAddress((void**)&wl1,  g_wl_w1);
    cudaGetSymbolAddress((void**)&wh2,  g_wh_w2);
    cudaGetSymbolAddress((void**)&wl2,  g_wl_w2);

    cudaFuncSetAttribute(tc_gemm<4,false,false,false>, cudaFuncAttributeMaxDynamicSharedMemorySize, SMEM_BYTES);
    cudaFuncSetAttribute(tc_gemm<4,true,false,false>,  cudaFuncAttributeMaxDynamicSharedMemorySize, SMEM_BYTES);
    cudaFuncSetAttribute(tc_gemm<1,false,true,true>,   cudaFuncAttributeMaxDynamicSharedMemorySize, SMEM_BYTES);

    pack_all<<<Lc*13*64, 256>>>(Wq, Wk, Wv1, Wv2, Wo, W1, W2);
    embed_kernel<<<TOK, 128>>>(x, ea, mask, node_W, node_b, edge_W, edge_b, no_edge);

    const dim3 ga(Nn, Hh, Bc);

    for (int l = 0; l < Lc; l++) {
        size_t t4Off = (size_t)l * 65536;   // 4-tile weight arrays
        size_t t1Off = (size_t)l * 16384;   // Wo
        size_t bOff  = (size_t)l * Dd;
        size_t b1Off = (size_t)l * FFc;

        // fused QKV: [TOK,128] @ [128,512], one CTA per 128-row block
        tc_gemm<4,false,false,false><<<256, 256, SMEM_BYTES>>>(
            tok, whq + t4Off, wlq + t4Off, nullptr, nullptr, nullptr, nullptr, qkv, 128);

        attn_s_kernel <<<ga, 256>>>();
        attn_ao_kernel<<<ga, 256>>>();

        // tok = LN(tok + o @ Wo + bo)
        tc_gemm<1,false,true,true><<<256, 256, SMEM_BYTES>>>(
            o, who + t1Off, wlo_ + t1Off, bo + bOff, tok, ln1g + bOff, ln1b + bOff, tok, 128);
        // hid = relu(tok @ W1 + b1)
        tc_gemm<4,true,false,false><<<256, 256, SMEM_BYTES>>>(
            tok, wh1 + t4Off, wl1 + t4Off, b1 + b1Off, nullptr, nullptr, nullptr, hid, 128);
        // tok = LN(tok + hid @ W2 + b2)
        tc_gemm<1,false,true,true><<<256, 256, SMEM_BYTES>>>(
            hid, wh2 + t4Off, wl2 + t4Off, b2 + bOff, tok, ln2g + bOff, ln2b + bOff, tok, 512);
    }

    out_kernel<<<(Bc*Nn*32 + 255)/256, 256>>>(Wout, bout, (float*)d_out);
}

// round 17
// speedup vs baseline: 2.1103x; 1.1039x over previous
#include <cuda_runtime.h>
#include <cuda_bf16.h>
#include <math.h>
#include <stdint.h>

// ---------------- problem constants ----------------
#define Bc   8
#define Nn   64
#define Dd   128
#define Hh   4
#define DHc  32
#define FFc  512
#define Lc   3
#define TOK  (Bc*Nn*Nn)              // 32768 tokens
#define QKVW 512
#define SCALE_INV 0.17677669529663687f

typedef unsigned long long ull;

// tcgen05 only in arch-specific passes (sm_103a cubin); compute_103 PTX gets fallback.
#if defined(__CUDA_ARCH__) && (defined(__CUDA_ARCH_FEAT_SM103_ALL) || \
    defined(__CUDA_ARCH_FEAT_SM100_ALL) || defined(__CUDA_ARCH_SPECIFIC__) || \
    defined(__CUDA_ARCH_FAMILY_SPECIFIC__))
#define TC_OK 1
#else
#define TC_OK 0
#endif

// ---------------- device scratch ----------------
__device__ float g_tok [TOK*Dd];                 // fp32 tok (residuals + readout)
__device__ float g_qkv [TOK*QKVW];               // fp32 q|k|v1|v2 for attention
__device__ float g_s   [Bc*Hh*Nn*Nn*Nn];         // scores, layout [b][h][i][l][j]
// activations as pre-swizzled bf16 hi/lo 128x128 tiles (32KB/tile)
__device__ __nv_bfloat16 g_ah_tok[256*16384],  g_al_tok[256*16384];
__device__ __nv_bfloat16 g_ah_o  [256*16384],  g_al_o  [256*16384];
__device__ __nv_bfloat16 g_ah_hid[1024*16384], g_al_hid[1024*16384];
// packed bf16 hi/lo weights, swizzled tiles
__device__ __nv_bfloat16 g_wh_qkv[Lc*4*16384], g_wl_qkv[Lc*4*16384];
__device__ __nv_bfloat16 g_wh_wo [Lc*1*16384], g_wl_wo [Lc*1*16384];
__device__ __nv_bfloat16 g_wh_w1 [Lc*4*16384], g_wl_w1 [Lc*4*16384];
__device__ __nv_bfloat16 g_wh_w2 [Lc*4*16384], g_wl_w2 [Lc*4*16384];

// ---------------- tcgen05 / async helpers ----------------
__device__ __forceinline__ uint32_t smem_u32(const void* p) {
    uint32_t a;
    asm("{ .reg .u64 t; cvta.to.shared.u64 t, %1; cvt.u32.u64 %0, t; }" : "=r"(a) : "l"(p));
    return a;
}
__device__ __forceinline__ uint32_t elect_one() {
    uint32_t pred;
    asm volatile("{\n\t.reg .pred p;\n\telect.sync _|p, 0xFFFFFFFF;\n\tselp.b32 %0, 1, 0, p;\n\t}" : "=r"(pred));
    return pred;
}
__device__ __forceinline__ void cp_async16(uint32_t dst, const void* src) {
    asm volatile("cp.async.cg.shared.global [%0], [%1], 16;" :: "r"(dst), "l"(src) : "memory");
}
#define CP_COMMIT()       asm volatile("cp.async.commit_group;" ::: "memory")
#define CP_WAIT0()        asm volatile("cp.async.wait_group 0;" ::: "memory")
#define TC_ALLOC(sa, n)   asm volatile("tcgen05.alloc.cta_group::1.sync.aligned.shared::cta.b32 [%0], %1;" :: "r"((uint32_t)(sa)), "r"((uint32_t)(n)) : "memory")
#define TC_DEALLOC(ta, n) asm volatile("tcgen05.dealloc.cta_group::1.sync.aligned.b32 %0, %1;" :: "r"(ta), "r"((uint32_t)(n)))
#define TC_COMMIT(mb)     asm volatile("tcgen05.commit.cta_group::1.mbarrier::arrive::one.shared::cluster.b64 [%0];" :: "r"((uint32_t)(mb)) : "memory")
#define TC_FENCE_AFTER()  asm volatile("tcgen05.fence::after_thread_sync;" ::: "memory")
#define TC_FENCE_BEFORE() asm volatile("tcgen05.fence::before_thread_sync;" ::: "memory")
#define TC_WAIT_LD()      asm volatile("tcgen05.wait::ld.sync.aligned;" ::: "memory")
#define FENCE_ASYNC()     asm volatile("fence.proxy.async.shared::cta;" ::: "memory")
#define MBAR_INIT(mb, c)  asm volatile("mbarrier.init.shared.b64 [%0], %1;" :: "r"((uint32_t)(mb)), "r"((uint32_t)(c)) : "memory")
#define MBAR_INVAL(mb)    asm volatile("mbarrier.inval.shared.b64 [%0];" :: "r"((uint32_t)(mb)) : "memory")

#define MBAR_WAIT(mb, par) do {                                              \
    uint32_t _mb = (uint32_t)(mb), _p = (uint32_t)(par), _done;              \
    asm volatile("{\n\t.reg .pred p;\n\t"                                    \
        "mbarrier.try_wait.parity.acquire.cta.shared::cta.b64 p, [%1], %2;\n\t" \
        "selp.b32 %0, 1, 0, p;\n\t}" : "=r"(_done) : "r"(_mb), "r"(_p) : "memory"); \
    if (!_done) {                                                            \
        asm volatile("{\n\t.reg .pred P1;\n\t"                               \
            "WAIT_LOOP_%=:\n\t"                                              \
            "mbarrier.try_wait.parity.acquire.cta.shared::cta.b64 P1, [%0], %1, 0x989680;\n\t" \
            "@P1 bra.uni WAIT_DONE_%=;\n\tbra.uni WAIT_LOOP_%=;\n\t"          \
            "WAIT_DONE_%=:\n\t}" :: "r"(_mb), "r"(_p) : "memory");           \
    }                                                                        \
} while (0)

#define TC_LD_X32(r, ta)                                                     \
    asm volatile("tcgen05.ld.sync.aligned.32x32b.x32.b32 "                   \
        "{%0, %1, %2, %3, %4, %5, %6, %7, "                                  \
        " %8, %9, %10, %11, %12, %13, %14, %15, "                            \
        " %16, %17, %18, %19, %20, %21, %22, %23, "                          \
        " %24, %25, %26, %27, %28, %29, %30, %31}, [%32];"                   \
        : "=r"((r)[0]),  "=r"((r)[1]),  "=r"((r)[2]),  "=r"((r)[3]),         \
          "=r"((r)[4]),  "=r"((r)[5]),  "=r"((r)[6]),  "=r"((r)[7]),         \
          "=r"((r)[8]),  "=r"((r)[9]),  "=r"((r)[10]), "=r"((r)[11]),        \
          "=r"((r)[12]), "=r"((r)[13]), "=r"((r)[14]), "=r"((r)[15]),        \
          "=r"((r)[16]), "=r"((r)[17]), "=r"((r)[18]), "=r"((r)[19]),        \
          "=r"((r)[20]), "=r"((r)[21]), "=r"((r)[22]), "=r"((r)[23]),        \
          "=r"((r)[24]), "=r"((r)[25]), "=r"((r)[26]), "=r"((r)[27]),        \
          "=r"((r)[28]), "=r"((r)[29]), "=r"((r)[30]), "=r"((r)[31])         \
        : "r"(ta))

#if TC_OK
__device__ __forceinline__ void mma_bf16_ss(uint32_t d, uint64_t ad, uint64_t bd,
                                            uint32_t idesc, uint32_t en) {
    asm volatile(
        "{\n\t.reg .pred p;\n\tsetp.ne.u32 p, %5, 0;\n\t"
        "tcgen05.mma.cta_group::1.kind::f16 [%0], %1, %2, %3, {%4, %4, %4, %4}, p;\n\t}"
        :: "r"(d), "l"(ad), "l"(bd), "r"(idesc), "r"(0u), "r"(en) : "memory");
}
#endif

// SW128 smem descriptor (layout=2, version=1, SBO=64, LBO=1)
__device__ __forceinline__ uint64_t smem_desc(uint32_t addr) {
    const uint64_t base = (uint64_t(2) << 61) | (uint64_t(1) << 46)
                        | (uint64_t(64) << 32) | (uint64_t(1) << 16);
    return base | ((uint64_t)(addr >> 4) & 0x3FFF);
}

// idesc: dtype F32, atype/btype BF16, N=128, M=128 (validated R11)
#define TC_IDESC ((1u<<4) | (1u<<7) | (1u<<10) | ((128u/8u)<<17) | ((128u/16u)<<24))

// blocked-atom SW128 byte offset for (row, col) in a 128x128 bf16 tile (validated R11)
__device__ __forceinline__ int tile_off(int row, int col) {
    int atom = (row >> 3) + (col >> 6) * 16;
    int off  = atom * 1024 + (row & 7) * 128 + (col & 63) * 2;
    return off ^ ((off >> 3) & 0x70);
}

// pack 8 fp32 -> 8 bf16 hi (uint4) + 8 bf16 lo (uint4), via bf16x2 converts
__device__ __forceinline__ void pack8(const float* v, uint4& h4, uint4& l4) {
    uint32_t hh[4], ll[4];
#pragma unroll
    for (int q = 0; q < 4; q++) {
        __nv_bfloat162 h2 = __float22bfloat162_rn(make_float2(v[2*q], v[2*q+1]));
        float2 hf = __bfloat1622float2(h2);
        __nv_bfloat162 l2 = __float22bfloat162_rn(make_float2(v[2*q] - hf.x, v[2*q+1] - hf.y));
        hh[q] = *(uint32_t*)&h2;
        ll[q] = *(uint32_t*)&l2;
    }
    h4 = make_uint4(hh[0], hh[1], hh[2], hh[3]);
    l4 = make_uint4(ll[0], ll[1], ll[2], ll[3]);
}

// ---------------- single fused weight-pack kernel ----------------
__global__ void pack_all(const float* __restrict__ Wq, const float* __restrict__ Wk,
                         const float* __restrict__ Wv1, const float* __restrict__ Wv2,
                         const float* __restrict__ Wo, const float* __restrict__ W1,
                         const float* __restrict__ W2)
{
    int idx = blockIdx.x * 256 + threadIdx.x;   // over Lc*13*16384
    int tile   = idx >> 14;
    int within = idx & 16383;
    int k = within & 127;
    int n = within >> 7;
    int l = tile / 13, u = tile - l * 13;

    float v;
    __nv_bfloat16 *dh, *dl;
    size_t dbase;
    if (u < 4) {
        const float* s = (u == 0) ? Wq : (u == 1) ? Wk : (u == 2) ? Wv1 : Wv2;
        v = s[(size_t)l*16384 + k*128 + n];
        dh = g_wh_qkv; dl = g_wl_qkv; dbase = (size_t)(l*4 + u) * 16384;
    } else if (u == 4) {
        v = Wo[(size_t)l*16384 + k*128 + n];
        dh = g_wh_wo; dl = g_wl_wo; dbase = (size_t)l * 16384;
    } else if (u < 9) {
        int nt = u - 5;
        v = W1[(size_t)l*65536 + (size_t)k*512 + nt*128 + n];
        dh = g_wh_w1; dl = g_wl_w1; dbase = (size_t)(l*4 + nt) * 16384;
    } else {
        int kc = u - 9;
        v = W2[(size_t)l*65536 + (size_t)(kc*128 + k)*128 + n];
        dh = g_wh_w2; dl = g_wl_w2; dbase = (size_t)(l*4 + kc) * 16384;
    }
    __nv_bfloat16 h  = __float2bfloat16(v);
    __nv_bfloat16 lo = __float2bfloat16(v - __bfloat162float(h));
    size_t di = dbase + (size_t)(tile_off(n, k) >> 1);
    dh[di] = h; dl[di] = lo;
}

// ---------------- tensor-core GEMM ----------------
// A pre-swizzled bf16 hi/lo tiles [mtile][KCH]; W tiles [nt][KCH].
// Out: optional fp32 C (N=NT*128 row-major) and/or bf16 hi/lo tiles [mtile][NT].
#define SM_AH  1024
#define SM_AL  (1024 + 32768)
#define SM_W   (1024 + 65536)         // + buf*65536 ; hi at +0, lo at +32768
#define SMEM_BYTES (1024 + 65536 + 2*65536)   // 197632

template<int NT, int KCH, bool RELU, bool RESID, bool LN, bool WF32, bool WTILE>
__global__ void __launch_bounds__(256)
tc_gemm(const __nv_bfloat16* __restrict__ Ahi, const __nv_bfloat16* __restrict__ Alo,
        const __nv_bfloat16* __restrict__ Whi, const __nv_bfloat16* __restrict__ Wlo,
        const float* __restrict__ bias, const float* __restrict__ resid,
        const float* __restrict__ lng,  const float* __restrict__ lnb,
        float* __restrict__ Cf, __nv_bfloat16* __restrict__ Chi, __nv_bfloat16* __restrict__ Clo)
{
    const int N = NT * 128;
    extern __shared__ char smem[];
    const int t = threadIdx.x, wid = t >> 5, lid = t & 31;
    const int bm0 = blockIdx.x * 128;
    const int wg  = wid >> 2;             // column half of a tile
    const int row = (wid & 3) * 32 + lid; // local row 0..127
    float v[64];

#if TC_OK
    uint32_t sb = smem_u32(smem);
    if (wid == 0) TC_ALLOC(sb, 512);
    if (t == 0) { MBAR_INIT(sb + 8, 1); MBAR_INIT(sb + 16, 1); }
    __syncthreads();
    uint32_t tmem;
    asm volatile("ld.shared.b32 %0, [%1];" : "=r"(tmem) : "r"(sb));

    int done = 0;   // completed MMA steps observed
#define WAIT_UNTIL(target) do { \
        while (done < (target)) { MBAR_WAIT(sb + 8 + (done & 1) * 8, (done >> 1) & 1); done++; } \
    } while (0)

    for (int kc = 0; kc < KCH; kc++) {
        WAIT_UNTIL(kc * NT);     // A buffer free
        {
            const char* srcH = (const char*)Ahi + (size_t)(blockIdx.x * KCH + kc) * 32768;
            const char* srcL = (const char*)Alo + (size_t)(blockIdx.x * KCH + kc) * 32768;
#pragma unroll
            for (int i = 0; i < 8; i++) {
                cp_async16(sb + SM_AH + (t + i*256)*16, srcH + (t + i*256)*16);
                cp_async16(sb + SM_AL + (t + i*256)*16, srcL + (t + i*256)*16);
            }
        }
#pragma unroll
        for (int nt = 0; nt < NT; nt++) {
            const int step = kc * NT + nt;
            if (step >= 2) WAIT_UNTIL(step - 1);     // W buffer (step&1) free
            {
                const int wb = (step & 1) * 65536;
                const char* srcH = (const char*)Whi + (size_t)(nt * KCH + kc) * 32768;
                const char* srcL = (const char*)Wlo + (size_t)(nt * KCH + kc) * 32768;
#pragma unroll
                for (int i = 0; i < 8; i++) {
                    cp_async16(sb + SM_W + wb + (t + i*256)*16,         srcH + (t + i*256)*16);
                    cp_async16(sb + SM_W + wb + 32768 + (t + i*256)*16, srcL + (t + i*256)*16);
                }
            }
            CP_COMMIT();
            CP_WAIT0();
            FENCE_ASYNC();
            __syncthreads();
            if (wid == 0 && elect_one()) {
                const int wb = (step & 1) * 65536;
                uint64_t ah = smem_desc(sb + SM_AH);
                uint64_t al = smem_desc(sb + SM_AL);
                uint64_t wh = smem_desc(sb + SM_W + wb);
                uint64_t wl = smem_desc(sb + SM_W + wb + 32768);
                uint32_t dD = tmem + nt * 128;
#pragma unroll
                for (int ks = 0; ks < 8; ks++) {
                    uint64_t off = (uint64_t)((ks >> 2) * 1024 + (ks & 3) * 2);
                    mma_bf16_ss(dD, ah + off, wh + off, TC_IDESC, (kc == 0 && ks == 0) ? 0u : 1u);
                    mma_bf16_ss(dD, ah + off, wl + off, TC_IDESC, 1u);
                    mma_bf16_ss(dD, al + off, wh + off, TC_IDESC, 1u);
                }
                TC_COMMIT(sb + 8 + (step & 1) * 8);
            }
        }
    }
    WAIT_UNTIL(KCH * NT);
#undef WAIT_UNTIL
    TC_FENCE_AFTER();
    __syncthreads();
#endif

    // ---- stage epilogue vectors ----
    float* sB  = (float*)(smem + 1024);   // [512]
    float* sG  = sB + 512;                // [128]
    float* sBt = sG + 128;                // [128]
    float* sS1 = sBt + 128;               // [128][2]
    float* sS2 = sS1 + 256;               // [128][2]
    for (int i = t; i < N; i += 256) sB[i] = bias ? bias[i] : 0.f;
    if (LN && t < 128) { sG[t] = lng[t]; sBt[t] = lnb[t]; }
    __syncthreads();

#pragma unroll
    for (int nt = 0; nt < NT; nt++) {
        const int colbase = nt * 128 + wg * 64;
#if TC_OK
        {
            uint32_t tmp[32];
            TC_LD_X32(tmp, tmem + nt * 128 + wg * 64);
            TC_WAIT_LD();
#pragma unroll
            for (int j = 0; j < 32; j++) v[j] = __uint_as_float(tmp[j]);
            TC_LD_X32(tmp, tmem + nt * 128 + wg * 64 + 32);
            TC_WAIT_LD();
#pragma unroll
            for (int j = 0; j < 32; j++) v[32 + j] = __uint_as_float(tmp[j]);
        }
#else
        // SIMT fallback (compute_103 PTX pass only; correct, not fast)
        for (int j = 0; j < 64; j++) v[j] = 0.f;
        for (int kc = 0; kc < KCH; kc++) {
            const char* ah = (const char*)Ahi + (size_t)(blockIdx.x * KCH + kc) * 32768;
            const char* al = (const char*)Alo + (size_t)(blockIdx.x * KCH + kc) * 32768;
            const char* wh = (const char*)Whi + (size_t)(nt * KCH + kc) * 32768;
            const char* wl = (const char*)Wlo + (size_t)(nt * KCH + kc) * 32768;
            for (int k = 0; k < 128; k++) {
                float a = __bfloat162float(*(const __nv_bfloat16*)(ah + tile_off(row, k)))
                        + __bfloat162float(*(const __nv_bfloat16*)(al + tile_off(row, k)));
                for (int j = 0; j < 64; j++)
                    v[j] += a * (__bfloat162float(*(const __nv_bfloat16*)(wh + tile_off(wg*64 + j, k)))
                               + __bfloat162float(*(const __nv_bfloat16*)(wl + tile_off(wg*64 + j, k))));
            }
        }
#endif
#pragma unroll
        for (int j = 0; j < 64; j++) v[j] += sB[colbase + j];
        if (RESID) {
#pragma unroll
            for (int j4 = 0; j4 < 16; j4++) {
                float4 r = *(const float4*)(resid + (size_t)(bm0 + row) * N + colbase + j4 * 4);
                v[j4*4+0] += r.x; v[j4*4+1] += r.y; v[j4*4+2] += r.z; v[j4*4+3] += r.w;
            }
        }
        if (RELU) {
#pragma unroll
            for (int j = 0; j < 64; j++) v[j] = fmaxf(v[j], 0.f);
        }
        if (LN) {
            float s1 = 0.f, s2 = 0.f;
#pragma unroll
            for (int j = 0; j < 64; j++) { s1 += v[j]; s2 += v[j]*v[j]; }
            sS1[row*2 + wg] = s1; sS2[row*2 + wg] = s2;
            __syncthreads();
            float ts1 = sS1[row*2] + sS1[row*2+1];
            float ts2 = sS2[row*2] + sS2[row*2+1];
            float mean = ts1 * (1.f/128.f);
            float var  = ts2 * (1.f/128.f) - mean*mean;
            float rstd = rsqrtf(var + 1e-5f);
#pragma unroll
            for (int j = 0; j < 64; j++)
                v[j] = (v[j] - mean) * rstd * sG[wg*64 + j] + sBt[wg*64 + j];
        }
        if (WF32) {
#pragma unroll
            for (int j4 = 0; j4 < 16; j4++)
                *(float4*)(Cf + (size_t)(bm0 + row) * N + colbase + j4 * 4) =
                    make_float4(v[j4*4+0], v[j4*4+1], v[j4*4+2], v[j4*4+3]);
        }
        if (WTILE) {
            char* dh = (char*)Chi + (size_t)(blockIdx.x * NT + nt) * 32768;
            char* dl = (char*)Clo + (size_t)(blockIdx.x * NT + nt) * 32768;
#pragma unroll
            for (int j8 = 0; j8 < 8; j8++) {
                uint4 h4, l4;
                pack8(v + j8*8, h4, l4);
                int off = tile_off(row, wg*64 + j8*8);
                *(uint4*)(dh + off) = h4;
                *(uint4*)(dl + off) = l4;
            }
        }
    }

#if TC_OK
    TC_FENCE_BEFORE();
    __syncthreads();
    if (t == 0) { MBAR_INVAL(sb + 8); MBAR_INVAL(sb + 16); }
    __syncthreads();
    if (wid == 0) TC_DEALLOC(tmem, 512);
#endif
}

// ---------------- embedding: fp32 tok + bf16 hi/lo tiles ----------------
__global__ void embed_kernel(const float* __restrict__ x,
                             const float* __restrict__ ea,
                             const unsigned int* __restrict__ mask,
                             const float* __restrict__ nW, const float* __restrict__ nb,
                             const float* __restrict__ eW, const float* __restrict__ eb,
                             const float* __restrict__ noe)
{
    int tkn = blockIdx.x;
    int b   = tkn >> 12;
    int ij  = tkn & 4095;
    int i   = ij >> 6, j = ij & 63;
    int d   = threadIdx.x;
    __shared__ float s_in[16];
    float out;
    if (i == j) {
        if (d < 16) s_in[d] = x[(b*Nn + i)*16 + d];
        __syncthreads();
        float acc = nb[d];
#pragma unroll
        for (int c = 0; c < 16; c++) acc += s_in[c] * nW[c*Dd + d];
        out = acc;
    } else {
        if (d < 8) s_in[d] = ea[tkn*8 + d];
        __syncthreads();
        if (mask[tkn] != 0u) {
            float acc = eb[d];
#pragma unroll
            for (int c = 0; c < 8; c++) acc += s_in[c] * eW[c*Dd + d];
            out = acc;
        } else {
            out = noe[d];
        }
    }
    g_tok[tkn*Dd + d] = out;
    // bf16 hi/lo tile write
    int rowl = tkn & 127, mt = tkn >> 7;
    __nv_bfloat16 h  = __float2bfloat16(out);
    __nv_bfloat16 lo = __float2bfloat16(out - __bfloat162float(h));
    int off = tile_off(rowl, d);
    *(__nv_bfloat16*)((char*)g_ah_tok + (size_t)mt*32768 + off) = h;
    *(__nv_bfloat16*)((char*)g_al_tok + (size_t)mt*32768 + off) = lo;
}

// ---------------- attention scores: write s[b][h][i][l][j] ----------------
__global__ void __launch_bounds__(256) attn_s_kernel()
{
    const int l = blockIdx.x, h = blockIdx.y, b = blockIdx.z;
    __shared__ float Qs[32][64];
    __shared__ float Ks[32][64];
    const int t = threadIdx.x;
    {
        int r  = t >> 2;
        int dq = (t & 3) * 8;
        const float* qp = g_qkv + ((size_t)((b*Nn + r)*Nn + l))*QKVW + h*DHc + dq;
        const float* kp = g_qkv + ((size_t)((b*Nn + l)*Nn + r))*QKVW + 128 + h*DHc + dq;
        float4 q0 = *(const float4*)qp, q1 = *(const float4*)(qp+4);
        float4 k0 = *(const float4*)kp, k1 = *(const float4*)(kp+4);
        Qs[dq+0][r]=q0.x; Qs[dq+1][r]=q0.y; Qs[dq+2][r]=q0.z; Qs[dq+3][r]=q0.w;
        Qs[dq+4][r]=q1.x; Qs[dq+5][r]=q1.y; Qs[dq+6][r]=q1.z; Qs[dq+7][r]=q1.w;
        Ks[dq+0][r]=k0.x; Ks[dq+1][r]=k0.y; Ks[dq+2][r]=k0.z; Ks[dq+3][r]=k0.w;
        Ks[dq+4][r]=k1.x; Ks[dq+5][r]=k1.y; Ks[dq+6][r]=k1.z; Ks[dq+7][r]=k1.w;
    }
    __syncthreads();
    const int tx = t & 15, ty = t >> 4;
    float acc[4][4];
#pragma unroll
    for (int i = 0; i < 4; i++)
#pragma unroll
        for (int j = 0; j < 4; j++) acc[i][j] = 0.f;
#pragma unroll
    for (int d = 0; d < 32; d++) {
        float4 a = *(const float4*)&Qs[d][ty*4];
        float4 c = *(const float4*)&Ks[d][tx*4];
        float av[4] = {a.x,a.y,a.z,a.w};
        float cv[4] = {c.x,c.y,c.z,c.w};
#pragma unroll
        for (int i = 0; i < 4; i++)
#pragma unroll
            for (int j = 0; j < 4; j++)
                acc[i][j] += av[i]*cv[j];
    }
    float* sp = g_s + (size_t)(b*Hh + h) * 262144 + (size_t)l * 64;
#pragma unroll
    for (int i = 0; i < 4; i++) {
        *(float4*)(sp + (size_t)(ty*4 + i)*4096 + tx*4) =
            make_float4(acc[i][0]*SCALE_INV, acc[i][1]*SCALE_INV,
                        acc[i][2]*SCALE_INV, acc[i][3]*SCALE_INV);
    }
}

// ---------------- softmax + o = sum_l a * (v1 ⊙ v2); o -> bf16 tiles ----------
__global__ void __launch_bounds__(256) attn_ao_kernel()
{
    const int i = blockIdx.x, h = blockIdx.y, b = blockIdx.z;
    __shared__ float Aa[64][64];
    __shared__ float V1s[64][32];
    __shared__ float redA[4][64];
    __shared__ float redB[4][64];
    const int t = threadIdx.x;
    {
        const int j = t & 63, g = t >> 6;
        const float* sp = g_s + (size_t)(b*Hh + h) * 262144 + (size_t)i * 4096 + j;
        float sv[16];
#pragma unroll
        for (int u = 0; u < 16; u++) sv[u] = sp[(g*16 + u) * 64];
        float m = sv[0];
#pragma unroll
        for (int u = 1; u < 16; u++) m = fmaxf(m, sv[u]);
        redA[g][j] = m;
        __syncthreads();
        float cm = fmaxf(fmaxf(redA[0][j], redA[1][j]), fmaxf(redA[2][j], redA[3][j]));
        float lsum = 0.f;
#pragma unroll
        for (int u = 0; u < 16; u++) { sv[u] = __expf(sv[u] - cm); lsum += sv[u]; }
        redB[g][j] = lsum;
        __syncthreads();
        float inv = 1.f / (redB[0][j] + redB[1][j] + redB[2][j] + redB[3][j]);
#pragma unroll
        for (int u = 0; u < 16; u++) Aa[g*16 + u][j] = sv[u] * inv;
    }
    {
        int l  = t >> 2;
        int dq = (t & 3) * 8;
        const float* vp = g_qkv + ((size_t)((b*Nn + i)*Nn + l))*QKVW + 256 + h*DHc + dq;
        *(float4*)&V1s[l][dq]   = *(const float4*)vp;
        *(float4*)&V1s[l][dq+4] = *(const float4*)(vp + 4);
    }
    __syncthreads();

    const int jj = t >> 2;
    const int dq = (t & 3) * 8;
    float acc[8];
#pragma unroll
    for (int u = 0; u < 8; u++) acc[u] = 0.f;
    const float* v2base = g_qkv + ((size_t)(b*Nn)*Nn + jj)*QKVW + 384 + h*DHc + dq;
#pragma unroll 4
    for (int l = 0; l < 64; l++) {
        float av = Aa[l][jj];
        float4 w0 = *(const float4*)&V1s[l][dq];
        float4 w1 = *(const float4*)&V1s[l][dq+4];
        float4 u0 = *(const float4*)(v2base + (size_t)l*Nn*QKVW);
        float4 u1 = *(const float4*)(v2base + (size_t)l*Nn*QKVW + 4);
        acc[0] += av * (w0.x * u0.x);
        acc[1] += av * (w0.y * u0.y);
        acc[2] += av * (w0.z * u0.z);
        acc[3] += av * (w0.w * u0.w);
        acc[4] += av * (w1.x * u1.x);
        acc[5] += av * (w1.y * u1.y);
        acc[6] += av * (w1.z * u1.z);
        acc[7] += av * (w1.w * u1.w);
    }
    // write o as bf16 hi/lo tile (16B block = one swizzle unit)
    int token = (b*Nn + i)*Nn + jj;
    int rowl = token & 127, mt = token >> 7;
    uint4 h4, l4;
    pack8(acc, h4, l4);
    int off = tile_off(rowl, h*DHc + dq);
    *(uint4*)((char*)g_ah_o + (size_t)mt*32768 + off) = h4;
    *(uint4*)((char*)g_al_o + (size_t)mt*32768 + off) = l4;
}

// ---------------- final readout ----------------
__global__ void out_kernel(const float* __restrict__ Wout,
                           const float* __restrict__ bout,
                           float* __restrict__ out)
{
    int w    = (blockIdx.x * blockDim.x + threadIdx.x) >> 5;
    int lane = threadIdx.x & 31;
    if (w >= Bc*Nn) return;
    int b = w >> 6, n = w & 63;
    const float* tp = g_tok + ((size_t)((b*Nn + n)*Nn + n)) * Dd;
    float4 tv = *(const float4*)(tp + lane*4);
    float4 wv = *(const float4*)(Wout + lane*4);
    float s = tv.x*wv.x + tv.y*wv.y + tv.z*wv.z + tv.w*wv.w;
#pragma unroll
    for (int m = 16; m > 0; m >>= 1) s += __shfl_xor_sync(0xffffffffu, s, m);
    if (lane == 0) out[w] = s + bout[0];
}

// ---------------- host launcher ----------------
extern "C" void kernel_launch(void* const* d_in, const int* in_sizes, int n_in,
                              void* d_out, int out_size)
{
    const float*        x        = (const float*)d_in[0];
    const float*        ea       = (const float*)d_in[1];
    const unsigned int* mask     = (const unsigned int*)d_in[2];
    const float*        node_W   = (const float*)d_in[3];
    const float*        node_b   = (const float*)d_in[4];
    const float*        edge_W   = (const float*)d_in[5];
    const float*        edge_b   = (const float*)d_in[6];
    const float*        no_edge  = (const float*)d_in[7];
    const float*        Wq       = (const float*)d_in[8];
    const float*        Wk       = (const float*)d_in[9];
    const float*        Wv1      = (const float*)d_in[10];
    const float*        Wv2      = (const float*)d_in[11];
    const float*        Wo       = (const float*)d_in[12];
    const float*        bo       = (const float*)d_in[13];
    const float*        ln1g     = (const float*)d_in[14];
    const float*        ln1b     = (const float*)d_in[15];
    const float*        W1       = (const float*)d_in[16];
    const float*        b1       = (const float*)d_in[17];
    const float*        W2       = (const float*)d_in[18];
    const float*        b2       = (const float*)d_in[19];
    const float*        ln2g     = (const float*)d_in[20];
    const float*        ln2b     = (const float*)d_in[21];
    const float*        Wout     = (const float*)d_in[22];
    const float*        bout     = (const float*)d_in[23];

    float *tok, *qkv;
    __nv_bfloat16 *ath, *atl, *aoh, *aol, *ahh, *ahl;
    __nv_bfloat16 *whq, *wlq, *who, *wlo_, *wh1, *wl1, *wh2, *wl2;
    cudaGetSymbolAddress((void**)&tok,  g_tok);
    cudaGetSymbolAddress((void**)&qkv,  g_qkv);
    cudaGetSymbolAddress((void**)&ath,  g_ah_tok);
    cudaGetSymbolAddress((void**)&atl,  g_al_tok);
    cudaGetSymbolAddress((void**)&aoh,  g_ah_o);
    cudaGetSymbolAddress((void**)&aol,  g_al_o);
    cudaGetSymbolAddress((void**)&ahh,  g_ah_hid);
    cudaGetSymbolAddress((void**)&ahl,  g_al_hid);
    cudaGetSymbolAddress((void**)&whq,  g_wh_qkv);
    cudaGetSymbolAddress((void**)&wlq,  g_wl_qkv);
    cudaGetSymbolAddress((void**)&who,  g_wh_wo);
    cudaGetSymbolAddress((void**)&wlo_, g_wl_wo);
    cudaGetSymbolAddress((void**)&wh1,  g_wh_w1);
    cudaGetSymbolAddress((void**)&wl1,  g_wl_w1);
    cudaGetSymbolAddress((void**)&wh2,  g_wh_w2);
    cudaGetSymbolAddress((void**)&wl2,  g_wl_w2);

    cudaFuncSetAttribute(tc_gemm<4,1,false,false,false,true,false>, cudaFuncAttributeMaxDynamicSharedMemorySize, SMEM_BYTES);
    cudaFuncSetAttribute(tc_gemm<1,1,false,true,true,true,true>,    cudaFuncAttributeMaxDynamicSharedMemorySize, SMEM_BYTES);
    cudaFuncSetAttribute(tc_gemm<4,1,true,false,false,false,true>,  cudaFuncAttributeMaxDynamicSharedMemorySize, SMEM_BYTES);
    cudaFuncSetAttribute(tc_gemm<1,4,false,true,true,true,true>,    cudaFuncAttributeMaxDynamicSharedMemorySize, SMEM_BYTES);

    pack_all<<<Lc*13*64, 256>>>(Wq, Wk, Wv1, Wv2, Wo, W1, W2);
    embed_kernel<<<TOK, 128>>>(x, ea, mask, node_W, node_b, edge_W, edge_b, no_edge);

    const dim3 ga(Nn, Hh, Bc);

    for (int l = 0; l < Lc; l++) {
        size_t t4Off = (size_t)l * 65536;
        size_t t1Off = (size_t)l * 16384;
        size_t bOff  = (size_t)l * Dd;
        size_t b1Off = (size_t)l * FFc;

        // qkv = tok @ Wqkv  (fp32 out for attention)
        tc_gemm<4,1,false,false,false,true,false><<<256, 256, SMEM_BYTES>>>(
            ath, atl, whq + t4Off, wlq + t4Off,
            nullptr, nullptr, nullptr, nullptr, qkv, nullptr, nullptr);

        attn_s_kernel <<<ga, 256>>>();
        attn_ao_kernel<<<ga, 256>>>();

        // tok = LN(tok + o @ Wo + bo)  -> fp32 + tiles
        tc_gemm<1,1,false,true,true,true,true><<<256, 256, SMEM_BYTES>>>(
            aoh, aol, who + t1Off, wlo_ + t1Off,
            bo + bOff, tok, ln1g + bOff, ln1b + bOff, tok, ath, atl);

        // hid = relu(tok @ W1 + b1)  -> tiles only
        tc_gemm<4,1,true,false,false,false,true><<<256, 256, SMEM_BYTES>>>(
            ath, atl, wh1 + t4Off, wl1 + t4Off,
            b1 + b1Off, nullptr, nullptr, nullptr, nullptr, ahh, ahl);

        // tok = LN(tok + hid @ W2 + b2)  -> fp32 + tiles
        tc_gemm<1,4,false,true,true,true,true><<<256, 256, SMEM_BYTES>>>(
            ahh, ahl, wh2 + t4Off, wl2 + t4Off,
            b2 + bOff, tok, ln2g + bOff, ln2b + bOff, tok, ath, atl);
    }

    out_kernel<<<(Bc*Nn*32 + 255)/256, 256>>>(Wout, bout, (float*)d_out);
}